// round 13
// baseline (speedup 1.0000x reference)
#include <cuda_runtime.h>
#include <math.h>

#define Bq 2048
#define Mq 64
#define Dq 64
#define BMq (Bq*Mq)
#define NPB (3*Bq*Dq)
#define ROWS 6144

// ---------------- device scratch ----------------
__device__ float g_embs[4*3*Bq*Dq];
__device__ float g_norm[4*3*Bq*Dq];
__device__ float g_rowsum[2*ROWS];
__device__ float g_colsum[2*ROWS];
__device__ float g_loss;
// packed tf32 W1 fragments, COALESCED layout:
// [(kk*4+tig)*64 + c] = (W1[kk*8+tig][c], W1[kk*8+tig+4][c])
__device__ uint2 g_w1p[2][4096];

__device__ __forceinline__ unsigned cvt_tf32(float x){
    unsigned r; asm("cvt.rna.tf32.f32 %0, %1;" : "=r"(r) : "f"(x)); return r;
}
__device__ __forceinline__ float cvt_tf32f(float x){ return __uint_as_float(cvt_tf32(x)); }

__device__ __forceinline__ void mma_tf32(float* c, const unsigned* a, unsigned b0, unsigned b1){
    asm volatile(
        "mma.sync.aligned.m16n8k8.row.col.f32.tf32.tf32.f32 "
        "{%0,%1,%2,%3}, {%4,%5,%6,%7}, {%8,%9}, {%0,%1,%2,%3};"
        : "+f"(c[0]), "+f"(c[1]), "+f"(c[2]), "+f"(c[3])
        : "r"(a[0]), "r"(a[1]), "r"(a[2]), "r"(a[3]), "r"(b0), "r"(b1));
}

__device__ __forceinline__ float wsum(float v){
#pragma unroll
    for (int o = 16; o; o >>= 1) v += __shfl_xor_sync(0xffffffffu, v, o);
    return v;
}
__device__ __forceinline__ void wsum5(float &a, float &b, float &c, float &d, float &e){
#pragma unroll
    for (int o = 16; o; o >>= 1){
        a += __shfl_xor_sync(0xffffffffu, a, o);
        b += __shfl_xor_sync(0xffffffffu, b, o);
        c += __shfl_xor_sync(0xffffffffu, c, o);
        d += __shfl_xor_sync(0xffffffffu, d, o);
        e += __shfl_xor_sync(0xffffffffu, e, o);
    }
}
__device__ __forceinline__ float wmax(float v){
#pragma unroll
    for (int o = 16; o; o >>= 1) v = fmaxf(v, __shfl_xor_sync(0xffffffffu, v, o));
    return v;
}
__device__ __forceinline__ int eidx(int bl, int l, int b, int j){
    return (((bl*3 + l)*Bq) + b)*Dq + j;
}
__device__ __forceinline__ float ftanh(float x){
    float e = __expf(2.f*x);
    return 1.f - 2.f/(e + 1.f);
}
__device__ __forceinline__ float fartanh_clip(float x){
    x = fminf(fmaxf(x, -1.f + 1e-5f), 1.f - 1e-5f);
    return 0.5f*__logf((1.f + x)/(1.f - x));
}

// ---------------- zero + weight packing ----------------
__global__ void zero_kernel(){
    int i = blockIdx.x*1024 + threadIdx.x;
    if (i < 2*ROWS){ g_rowsum[i] = 0.f; g_colsum[i] = 0.f; }
    if (i == 0) g_loss = 0.f;
}
__global__ void packw_kernel(const float* __restrict__ Wa, const float* __restrict__ Wb){
    int idx = blockIdx.x*256 + threadIdx.x;          // 8192 total
    int which = idx >> 12, entry = idx & 4095;
    int slot = entry >> 6, c = entry & 63;           // entry = slot*64 + c
    int kk = slot >> 2, tig = slot & 3;
    const float* W = which ? Wb : Wa;
    int kb = kk*8 + tig;
    uint2 v;
    v.x = cvt_tf32(W[kb*64 + c]);
    v.y = cvt_tf32(W[(kb+4)*64 + c]);
    g_w1p[which][entry] = v;
}

// ---------------- init embeddings + fused normalize ----------------
__global__ __launch_bounds__(256) void init_kernel(
    const float* __restrict__ E, const int* __restrict__ items,
    const int* __restrict__ ucf_h, const int* __restrict__ ukg_h,
    const int* __restrict__ icf_h){
    __shared__ float pp[3][4][68];
    __shared__ float rows[4][68];
    __shared__ float inr[4];
    int b = blockIdx.x, tid = threadIdx.x;
    int j = tid & 63, q = tid >> 6;
    int lane = tid & 31, wid = tid >> 5;
    float s0 = 0.f, s2 = 0.f, s3 = 0.f;
#pragma unroll 4
    for (int mm = 0; mm < 16; ++mm){
        int m = q*16 + mm;
        s0 += E[ucf_h[b*Mq + m]*Dq + j];
        s2 += E[ukg_h[b*Mq + m]*Dq + j];
        s3 += E[icf_h[b*Mq + m]*Dq + j];
    }
    pp[0][q][j] = s0; pp[1][q][j] = s2; pp[2][q][j] = s3;
    __syncthreads();
    if (tid < 64){
        const float inv = 1.f/64.f;
        rows[0][tid] = (pp[0][0][tid]+pp[0][1][tid]+pp[0][2][tid]+pp[0][3][tid])*inv;
        rows[1][tid] = E[items[b]*Dq + tid];
        rows[2][tid] = (pp[1][0][tid]+pp[1][1][tid]+pp[1][2][tid]+pp[1][3][tid])*inv;
        rows[3][tid] = (pp[2][0][tid]+pp[2][1][tid]+pp[2][2][tid]+pp[2][3][tid])*inv;
    }
    __syncthreads();
    if (wid < 4){
        float v = rows[wid][lane]*rows[wid][lane] + rows[wid][lane+32]*rows[wid][lane+32];
        v = wsum(v);
        if (lane == 0) inr[wid] = 1.f/fmaxf(sqrtf(v), 1e-12f);
    }
    __syncthreads();
    if (tid < 64){
#pragma unroll
        for (int bl = 0; bl < 4; ++bl){
            float o = rows[bl][tid];
            g_embs[eidx(bl,0,b,tid)] = o;
            g_norm[eidx(bl,0,b,tid)] = o*inr[bl];
        }
    }
}

// ---------------- unified aggregation kernel (R9 structure) ----------------
#define AGG_SMEM_FLOATS (64*132 + 64*68 + 64 + 64 + 4*68 + 64*3 + 16)

__device__ __forceinline__ void ed_body(
    float* sm, int b, int layer, int build,
    const float* __restrict__ E, const float* __restrict__ R,
    const int* __restrict__ hI, const int* __restrict__ rI, const int* __restrict__ tI,
    const float* __restrict__ W2)
{
    float* xs = sm;                     // [64][132] tf32
    float* ts = xs + 64*132;            // [64][68]
    float* av = ts + 64*68;             // [64]
    float* wv = av + 64;                // [64]
    float* pp = wv + 64;                // [4][68]

    const int tid = threadIdx.x, lane = tid & 31, wid = tid >> 5;
    const int gid = lane >> 2, tig = lane & 3;

    if (tid < 64) av[tid] = 0.f;

    for (int e = tid; e < 1024; e += 256){
        int m = e & 63, k4 = e >> 6;
        float4 hv = *(const float4*)&E[hI[b*Mq + m]*Dq + k4*4];
        float4 pv = *(const float4*)&R[rI[b*Mq + m]*Dq + k4*4];
        if (layer){
            float4 h2 = *(const float4*)&E[hI[BMq + b*Mq + m]*Dq + k4*4];
            hv.x += h2.x; hv.y += h2.y; hv.z += h2.z; hv.w += h2.w;
            float4 p2 = *(const float4*)&R[rI[BMq + b*Mq + m]*Dq + k4*4];
            pv.x *= p2.x; pv.y *= p2.y; pv.z *= p2.z; pv.w *= p2.w;
        }
        float4 tv = *(const float4*)&E[tI[layer*BMq + b*Mq + m]*Dq + k4*4];
        float4 hc = make_float4(cvt_tf32f(hv.x), cvt_tf32f(hv.y), cvt_tf32f(hv.z), cvt_tf32f(hv.w));
        float4 pc = make_float4(cvt_tf32f(pv.x), cvt_tf32f(pv.y), cvt_tf32f(pv.z), cvt_tf32f(pv.w));
        *(float4*)&xs[m*132 + k4*4]      = hc;
        *(float4*)&xs[m*132 + 64 + k4*4] = pc;
        *(float4*)&ts[m*68 + k4*4] = tv;
    }
    __syncthreads();

    // phase 2: 2(M) x 4(N) split, scalar LDS.32 fragments, coalesced packed W1
    {
        const int m0 = (wid & 1)*32, n0 = (wid >> 1)*16;
        float acc[2][2][4] = {};
#pragma unroll
        for (int kk = 0; kk < 16; ++kk){
            unsigned a[2][4];
#pragma unroll
            for (int mi = 0; mi < 2; ++mi){
                int base = (m0 + mi*16 + gid)*132 + kk*8 + tig;
                a[mi][0] = __float_as_uint(xs[base]);
                a[mi][1] = __float_as_uint(xs[base + 8*132]);
                a[mi][2] = __float_as_uint(xs[base + 4]);
                a[mi][3] = __float_as_uint(xs[base + 8*132 + 4]);
            }
            int slot = kk*4 + tig;
#pragma unroll
            for (int ni = 0; ni < 2; ++ni){
                int c = n0 + ni*8 + gid;
                uint2 bv = __ldg(&g_w1p[0][slot*64 + c]);
                mma_tf32(acc[0][ni], a[0], bv.x, bv.y);
                mma_tf32(acc[1][ni], a[1], bv.x, bv.y);
            }
        }
#pragma unroll
        for (int mi = 0; mi < 2; ++mi){
            float slo = 0.f, shi = 0.f;
#pragma unroll
            for (int ni = 0; ni < 2; ++ni){
                int c = n0 + ni*8 + tig*2;
                float w2a = __ldg(&W2[c]), w2b = __ldg(&W2[c+1]);
                slo += fmaxf(acc[mi][ni][0],0.f)*w2a + fmaxf(acc[mi][ni][1],0.f)*w2b;
                shi += fmaxf(acc[mi][ni][2],0.f)*w2a + fmaxf(acc[mi][ni][3],0.f)*w2b;
            }
            slo += __shfl_xor_sync(0xffffffffu, slo, 1);
            slo += __shfl_xor_sync(0xffffffffu, slo, 2);
            shi += __shfl_xor_sync(0xffffffffu, shi, 1);
            shi += __shfl_xor_sync(0xffffffffu, shi, 2);
            if (tig == 0){
                atomicAdd(&av[m0 + mi*16 + gid],     slo);
                atomicAdd(&av[m0 + mi*16 + gid + 8], shi);
            }
        }
    }
    __syncthreads();

    if (wid == 0){
        float a0 = 1.f/(1.f + __expf(-av[lane]));
        float a1 = 1.f/(1.f + __expf(-av[lane+32]));
        float mx = wmax(fmaxf(a0, a1));
        float e0 = __expf(a0 - mx), e1 = __expf(a1 - mx);
        float s = wsum(e0 + e1);
        wv[lane] = e0/s; wv[lane+32] = e1/s;
    }
    __syncthreads();

    {
        int j = tid & 63, q = tid >> 6;
        float o = 0.f;
#pragma unroll 4
        for (int mm = 0; mm < 16; ++mm){
            int m = q*16 + mm;
            o += wv[m]*ts[m*68 + j];
        }
        pp[q*68 + j] = o;
    }
    __syncthreads();
    if (tid < 64) av[tid] = pp[tid] + pp[68+tid] + pp[136+tid] + pp[204+tid];
    __syncthreads();
    if (wid == 0){
        float v = av[lane]*av[lane] + av[lane+32]*av[lane+32];
        v = wsum(v);
        if (lane == 0) wv[0] = 1.f/fmaxf(sqrtf(v), 1e-12f);
    }
    __syncthreads();
    if (tid < 64){
        float o = av[tid];
        g_embs[eidx(build, layer+1, b, tid)] = o;
        g_norm[eidx(build, layer+1, b, tid)] = o*wv[0];
    }
}

__device__ __forceinline__ void hyper_body(
    float* sm, int b, int layer, int build,
    const float* __restrict__ E, const float* __restrict__ R,
    const int* __restrict__ hI, const int* __restrict__ rI, const int* __restrict__ tI,
    const float* __restrict__ B1,
    const float* __restrict__ W2, const float* __restrict__ B2,
    const float* __restrict__ curv)
{
    float* tang = sm;                   // [64][132] tf32-rounded
    float* hts  = tang + 64*132;        // [64][65] inside [64][68]
    float* av   = hts + 64*68;          // [64]
    float* wv   = av + 64;              // [64]
    float* pp   = wv + 64;              // [4][68]
    float* mp   = pp + 4*68;            // [64]
    float* ht2s = mp + 64;              // [64]
    float* istg = ht2s + 64;            // [64]
    float* scal = istg + 64;            // [16]

    const int tid = threadIdx.x, lane = tid & 31, wid = tid >> 5;
    const int gid = lane >> 2, tig = lane & 3;

    const float absc = fabsf(curv[0]);
    const float th1  = 0.761594155955765f;
    const float sh0  = th1*absc;
    const float hh2  = sh0*sh0;
    const float lam  = 2.f/fmaxf(1.f - hh2, 1e-15f);
    const float tyc  = ftanh(lam*0.5f);
    const float y2c  = tyc*tyc;
    const float c2c  = 1.f - hh2;

    if (tid < 64) av[tid] = 0.f;

    const float2* E2 = (const float2*)E;
    const float2* R2 = (const float2*)R;

#pragma unroll 2
    for (int r = 0; r < 8; ++r){
        int m = wid*8 + r;
        float2 h2v = E2[hI[b*Mq + m]*32 + lane];
        float2 p2v = R2[rI[b*Mq + m]*32 + lane];
        if (layer){
            float2 hB = E2[hI[BMq + b*Mq + m]*32 + lane];
            h2v.x += hB.x; h2v.y += hB.y;
            float2 pB = R2[rI[BMq + b*Mq + m]*32 + lane];
            p2v.x *= pB.x; p2v.y *= pB.y;
        }
        float2 t2v = E2[tI[layer*BMq + b*Mq + m]*32 + lane];
        float hv0 = h2v.x, hv1 = h2v.y;
        float pv0 = p2v.x, pv1 = p2v.y;
        float tv0 = t2v.x, tv1 = t2v.y;

        float nh2 = hv0*hv0 + hv1*hv1;
        float np2 = pv0*pv0 + pv1*pv1;
        float nt2 = tv0*tv0 + tv1*tv1;
        float dht = hv0*tv0 + hv1*tv1;
        float dhp = hv0*pv0 + hv1*pv1;
        wsum5(nh2, np2, nt2, dht, dhp);

        float ih = 1.f/fmaxf(sqrtf(nh2), 1e-12f);
        float ip = 1.f/fmaxf(sqrtf(np2), 1e-12f);
        float it = 1.f/fmaxf(sqrtf(nt2), 1e-12f);

        float sh = sh0*ih;
        float sy = tyc*it;
        float sq = tyc*ip;

        float xy = sh*sy*dht;
        float xq = sh*sq*dhp;

        float c1 = 1.f + 2.f*xy + y2c;
        float den = fmaxf(1.f + 2.f*xy + hh2*y2c, 1e-15f);
        float invden = 1.f/den;
        float ht0 = (c1*sh*hv0 + c2c*sy*tv0)*invden;
        float ht1 = (c1*sh*hv1 + c2c*sy*tv1)*invden;
        float ht2 = (c1*c1*hh2 + 2.f*c1*c2c*xy + c2c*c2c*y2c)*invden*invden;

        float d1 = 1.f + 2.f*xq + y2c;
        float dd = fmaxf(1.f + 2.f*xq + hh2*y2c, 1e-15f);
        float invdd = 1.f/dd;
        float hr0 = (d1*sh*hv0 + c2c*sq*pv0)*invdd;
        float hr1 = (d1*sh*hv1 + c2c*sq*pv1)*invdd;
        float hr2 = (d1*d1*hh2 + 2.f*d1*c2c*xq + c2c*c2c*y2c)*invdd*invdd;

        float n128 = sqrtf(fmaxf(hh2 + hr2, 1e-15f));
        float stg = fartanh_clip(n128)/n128;

        hts[m*65 + 2*lane] = ht0; hts[m*65 + 2*lane + 1] = ht1;
        if (lane == 0){ ht2s[m] = ht2; istg[m] = 1.f/stg; }
        *(float2*)&tang[m*132 + 2*lane] =
            make_float2(cvt_tf32f(stg*sh*hv0), cvt_tf32f(stg*sh*hv1));
        *(float2*)&tang[m*132 + 64 + 2*lane] =
            make_float2(cvt_tf32f(stg*hr0), cvt_tf32f(stg*hr1));
    }
    __syncthreads();

    // phase 2: 2(M) x 4(N) split, scalar LDS.32 fragments, coalesced packed W1
    {
        const int m0 = (wid & 1)*32, n0 = (wid >> 1)*16;
        float acc[2][2][4] = {};
#pragma unroll
        for (int kk = 0; kk < 16; ++kk){
            unsigned a[2][4];
#pragma unroll
            for (int mi = 0; mi < 2; ++mi){
                int base = (m0 + mi*16 + gid)*132 + kk*8 + tig;
                a[mi][0] = __float_as_uint(tang[base]);
                a[mi][1] = __float_as_uint(tang[base + 8*132]);
                a[mi][2] = __float_as_uint(tang[base + 4]);
                a[mi][3] = __float_as_uint(tang[base + 8*132 + 4]);
            }
            int slot = kk*4 + tig;
#pragma unroll
            for (int ni = 0; ni < 2; ++ni){
                int c = n0 + ni*8 + gid;
                uint2 bv = __ldg(&g_w1p[1][slot*64 + c]);
                mma_tf32(acc[0][ni], a[0], bv.x, bv.y);
                mma_tf32(acc[1][ni], a[1], bv.x, bv.y);
            }
        }
#pragma unroll
        for (int mi = 0; mi < 2; ++mi){
            float slo = 0.f, shi = 0.f;
#pragma unroll
            for (int ni = 0; ni < 2; ++ni){
                int c = n0 + ni*8 + tig*2;
                float w2a = __ldg(&W2[c]), w2b = __ldg(&W2[c+1]);
                float b1a = __ldg(&B1[c]), b1b = __ldg(&B1[c+1]);
                slo += fmaxf(acc[mi][ni][0] + b1a, 0.f)*w2a + fmaxf(acc[mi][ni][1] + b1b, 0.f)*w2b;
                shi += fmaxf(acc[mi][ni][2] + b1a, 0.f)*w2a + fmaxf(acc[mi][ni][3] + b1b, 0.f)*w2b;
            }
            slo += __shfl_xor_sync(0xffffffffu, slo, 1);
            slo += __shfl_xor_sync(0xffffffffu, slo, 2);
            shi += __shfl_xor_sync(0xffffffffu, shi, 1);
            shi += __shfl_xor_sync(0xffffffffu, shi, 2);
            if (tig == 0){
                atomicAdd(&av[m0 + mi*16 + gid],     slo);
                atomicAdd(&av[m0 + mi*16 + gid + 8], shi);
            }
        }
    }
    __syncthreads();

    if (wid == 0){
        const float b2 = B2[0];
        float a0 = ftanh(av[lane] + b2);
        float a1 = ftanh(av[lane+32] + b2);
        float mx = wmax(fmaxf(a0, a1));
        float e0 = __expf(a0 - mx), e1 = __expf(a1 - mx);
        float s = wsum(e0 + e1);
        wv[lane] = e0/s; wv[lane+32] = e1/s;
    }
    __syncthreads();

    // phase 3
    if (tid < 64) av[tid] = wv[tid]*istg[tid];
    __syncthreads();
    {
        int j = tid & 63, q = tid >> 6;
        float a = 0.f;
#pragma unroll 4
        for (int mm = 0; mm < 16; ++mm){
            int m = q*16 + mm;
            a += av[m]*tang[m*132 + j];
        }
        pp[q*68 + j] = a;
    }
    __syncthreads();
    if (tid < 64) mp[tid] = pp[tid] + pp[68+tid] + pp[136+tid] + pp[204+tid];
    __syncthreads();
    if (wid == 0){
        float v = mp[lane]*mp[lane] + mp[lane+32]*mp[lane+32];
        v = wsum(v);
        if (lane == 0) scal[0] = v;
    }
    __syncthreads();
    {
        int m = tid & 63, q = tid >> 6;
        float a = 0.f;
#pragma unroll 4
        for (int jj = 0; jj < 16; ++jj){
            int j = q*16 + jj;
            a += hts[m*65 + j]*mp[j];
        }
        pp[q*68 + m] = a;
    }
    __syncthreads();
    if (tid < 64){
        float dsum = pp[tid] + pp[68+tid] + pp[136+tid] + pp[204+tid];
        float p2v = scal[0];
        float wm = wv[tid];
        float xy = -wm*dsum;
        float y2 = wm*wm*ht2s[tid];
        float c2v = 1.f - p2v;
        float c1v = 1.f + 2.f*xy + y2;
        float den = fmaxf(1.f + 2.f*xy + p2v*y2, 1e-15f);
        float invden = 1.f/den;
        float n2 = (c1v*c1v*p2v + 2.f*c1v*c2v*xy + c2v*c2v*y2)*invden*invden;
        float n = sqrtf(fmaxf(n2, 1e-15f));
        float lamp = 2.f/fmaxf(1.f - p2v, 1e-15f);
        float sc = (2.f/lamp)*fartanh_clip(n)/n;
        av[tid]   = wm*sc*c1v*invden;    // alv
        istg[tid] = wm*wm*sc*c2v*invden; // bev
    }
    __syncthreads();
    if (wid == 0){
        float sa = av[lane] + av[lane+32];
        sa = wsum(sa);
        if (lane == 0) scal[1] = sa;
    }
    __syncthreads();
    {
        int j = tid & 63, q = tid >> 6;
        float o = 0.f;
#pragma unroll 4
        for (int mm = 0; mm < 16; ++mm){
            int m = q*16 + mm;
            o += istg[m]*hts[m*65 + j];
        }
        pp[q*68 + j] = o;
    }
    __syncthreads();
    if (tid < 64)
        ht2s[tid] = (pp[tid] + pp[68+tid] + pp[136+tid] + pp[204+tid]) - mp[tid]*scal[1];
    __syncthreads();
    if (wid == 0){
        float v = ht2s[lane]*ht2s[lane] + ht2s[lane+32]*ht2s[lane+32];
        v = wsum(v);
        if (lane == 0) scal[2] = 1.f/fmaxf(sqrtf(v), 1e-12f);
    }
    __syncthreads();
    if (tid < 64){
        float o = ht2s[tid];
        g_embs[eidx(build, layer+1, b, tid)] = o;
        g_norm[eidx(build, layer+1, b, tid)] = o*scal[2];
    }
}

__global__ __launch_bounds__(256) void agg_kernel(
    const float* __restrict__ E, const float* __restrict__ R,
    const int* __restrict__ ucf_h, const int* __restrict__ ucf_r, const int* __restrict__ ucf_t,
    const int* __restrict__ ikg_h, const int* __restrict__ ikg_r, const int* __restrict__ ikg_t,
    const int* __restrict__ ukg_h, const int* __restrict__ ukg_r, const int* __restrict__ ukg_t,
    const int* __restrict__ icf_h, const int* __restrict__ icf_r, const int* __restrict__ icf_t,
    const float* __restrict__ att_w2,
    const float* __restrict__ a2_b1,
    const float* __restrict__ a2_w2, const float* __restrict__ a2_b2,
    const float* __restrict__ curv)
{
    extern __shared__ float sm[];
    const int b = blockIdx.x, layer = blockIdx.y, z = blockIdx.z;
    if (z == 0)      ed_body(sm, b, layer, 0, E, R, ucf_h, ucf_r, ucf_t, att_w2);
    else if (z == 1) ed_body(sm, b, layer, 1, E, R, ikg_h, ikg_r, ikg_t, att_w2);
    else if (z == 2) hyper_body(sm, b, layer, 2, E, R, ukg_h, ukg_r, ukg_t, a2_b1, a2_w2, a2_b2, curv);
    else             hyper_body(sm, b, layer, 3, E, R, icf_h, icf_r, icf_t, a2_b1, a2_w2, a2_b2, curv);
}

// ---------------- MLCL GEMM: 64x128 tiles, coalesced staging, scalar frags ----------------
#define ML_SMEM_FLOATS (64*68 + 128*68 + 64 + 128)
__global__ __launch_bounds__(256) void mlcl_gemm(){
    const int pair = blockIdx.z;
    const float* A  = g_norm + (pair == 0 ? 0 : 1)*NPB;
    const float* Bn = g_norm + (pair == 0 ? 2 : 3)*NPB;
    float* rs = g_rowsum + pair*ROWS;
    float* cs = g_colsum + pair*ROWS;

    extern __shared__ float sm[];
    float* As = sm;                 // [64][68] tf32
    float* Bs = As + 64*68;         // [128][68] tf32
    float* rowpart = Bs + 128*68;   // [64]
    float* colpart = rowpart + 64;  // [128]

    const int tid = threadIdx.x;
    const int by = blockIdx.y, bx = blockIdx.x;
    const int lane = tid & 31, wid = tid >> 5;
    const int gid = lane >> 2, tig = lane & 3;

    for (int e = tid; e < 1024; e += 256){
        int i = e >> 4, k4 = e & 15;
        float4 v = *(const float4*)&A[(by*64 + i)*64 + k4*4];
        *(float4*)&As[i*68 + k4*4] =
            make_float4(cvt_tf32f(v.x), cvt_tf32f(v.y), cvt_tf32f(v.z), cvt_tf32f(v.w));
    }
    for (int e = tid; e < 2048; e += 256){
        int i = e >> 4, k4 = e & 15;
        float4 v = *(const float4*)&Bn[(bx*128 + i)*64 + k4*4];
        *(float4*)&Bs[i*68 + k4*4] =
            make_float4(cvt_tf32f(v.x), cvt_tf32f(v.y), cvt_tf32f(v.z), cvt_tf32f(v.w));
    }
    if (tid < 64) rowpart[tid] = 0.f;
    if (tid < 128) colpart[tid] = 0.f;
    __syncthreads();

    const int m0 = (wid & 3)*16, n0 = (wid >> 2)*64;
    float acc[8][4] = {};
#pragma unroll
    for (int kk = 0; kk < 8; ++kk){
        int abase = (m0 + gid)*68 + kk*8 + tig;
        unsigned a[4] = { __float_as_uint(As[abase]),
                          __float_as_uint(As[abase + 8*68]),
                          __float_as_uint(As[abase + 4]),
                          __float_as_uint(As[abase + 8*68 + 4]) };
#pragma unroll
        for (int ni = 0; ni < 8; ++ni){
            int bb = (n0 + ni*8 + gid)*68 + kk*8 + tig;
            mma_tf32(acc[ni], a, __float_as_uint(Bs[bb]), __float_as_uint(Bs[bb + 4]));
        }
    }

    // fused exp(*5) row/col sums
    float cl[8], ch[8];
#pragma unroll
    for (int ni = 0; ni < 8; ++ni){ cl[ni] = 0.f; ch[ni] = 0.f; }
    float rlo = 0.f, rhi = 0.f;
#pragma unroll
    for (int ni = 0; ni < 8; ++ni){
        float e0 = __expf(5.f*acc[ni][0]);
        float e1 = __expf(5.f*acc[ni][1]);
        float e2 = __expf(5.f*acc[ni][2]);
        float e3 = __expf(5.f*acc[ni][3]);
        rlo += e0 + e1; rhi += e2 + e3;
        cl[ni] += e0 + e2; ch[ni] += e1 + e3;
    }
    rlo += __shfl_xor_sync(0xffffffffu, rlo, 1);
    rlo += __shfl_xor_sync(0xffffffffu, rlo, 2);
    rhi += __shfl_xor_sync(0xffffffffu, rhi, 1);
    rhi += __shfl_xor_sync(0xffffffffu, rhi, 2);
    if (tig == 0){
        atomicAdd(&rowpart[m0 + gid],     rlo);
        atomicAdd(&rowpart[m0 + gid + 8], rhi);
    }
#pragma unroll
    for (int ni = 0; ni < 8; ++ni){
        cl[ni] += __shfl_xor_sync(0xffffffffu, cl[ni], 4);
        cl[ni] += __shfl_xor_sync(0xffffffffu, cl[ni], 8);
        cl[ni] += __shfl_xor_sync(0xffffffffu, cl[ni], 16);
        ch[ni] += __shfl_xor_sync(0xffffffffu, ch[ni], 4);
        ch[ni] += __shfl_xor_sync(0xffffffffu, ch[ni], 8);
        ch[ni] += __shfl_xor_sync(0xffffffffu, ch[ni], 16);
        if (gid == 0){
            atomicAdd(&colpart[n0 + ni*8 + tig*2],     cl[ni]);
            atomicAdd(&colpart[n0 + ni*8 + tig*2 + 1], ch[ni]);
        }
    }
    __syncthreads();
    if (tid < 64)  atomicAdd(&rs[by*64  + tid], rowpart[tid]);
    if (tid < 128) atomicAdd(&cs[bx*128 + tid], colpart[tid]);
}

// ---------------- loss reduction ----------------
__global__ void loss_kernel(){
    const int wid = threadIdx.x >> 5, lane = threadIdx.x & 31;
    int r = blockIdx.x*8 + wid;
    int pair = r >= ROWS;
    int i = r - pair*ROWS;
    const float* A  = g_norm + (pair ? 1 : 0)*NPB;
    const float* Bn = g_norm + (pair ? 3 : 2)*NPB;
    float d = A[i*64 + lane]*Bn[i*64 + lane] + A[i*64 + lane + 32]*Bn[i*64 + lane + 32];
    d = wsum(d);
    __shared__ float red[8];
    if (lane == 0)
        red[wid] = logf(g_rowsum[pair*ROWS + i]) + logf(g_colsum[pair*ROWS + i]) - 10.f*d;
    __syncthreads();
    if (threadIdx.x == 0){
        float s = 0.f;
#pragma unroll
        for (int w = 0; w < 8; ++w) s += red[w];
        atomicAdd(&g_loss, s);
    }
}

// ---------------- scores + loss finalize ----------------
__global__ void scores_kernel(float* out, int out_size){
    int b = blockIdx.x*8 + (threadIdx.x >> 5);
    int lane = threadIdx.x & 31;
    if (blockIdx.x == 0 && threadIdx.x == 0 && out_size > Bq) out[Bq] = 1e-6f*g_loss;
    if (b >= Bq) return;
    float s = 0.f;
#pragma unroll
    for (int l = 0; l < 3; ++l){
        s += g_embs[eidx(0,l,b,lane)]   *g_embs[eidx(3,l,b,lane)]
           + g_embs[eidx(0,l,b,lane+32)]*g_embs[eidx(3,l,b,lane+32)]
           + g_embs[eidx(2,l,b,lane)]   *g_embs[eidx(1,l,b,lane)]
           + g_embs[eidx(2,l,b,lane+32)]*g_embs[eidx(1,l,b,lane+32)];
    }
    s = wsum(s);
    if (lane == 0) out[b] = 1.f/(1.f + expf(-s));
}

// ---------------- launch ----------------
extern "C" void kernel_launch(void* const* d_in, const int* in_sizes, int n_in,
                              void* d_out, int out_size){
    (void)in_sizes; (void)n_in;
    const int*   items  = (const int*)  d_in[0];
    const int*   ucf_h  = (const int*)  d_in[1];
    const int*   ucf_r  = (const int*)  d_in[2];
    const int*   ucf_t  = (const int*)  d_in[3];
    const int*   ikg_h  = (const int*)  d_in[4];
    const int*   ikg_r  = (const int*)  d_in[5];
    const int*   ikg_t  = (const int*)  d_in[6];
    const int*   ukg_h  = (const int*)  d_in[7];
    const int*   ukg_r  = (const int*)  d_in[8];
    const int*   ukg_t  = (const int*)  d_in[9];
    const int*   icf_h  = (const int*)  d_in[10];
    const int*   icf_r  = (const int*)  d_in[11];
    const int*   icf_t  = (const int*)  d_in[12];
    const float* E      = (const float*)d_in[13];
    const float* R      = (const float*)d_in[14];
    const float* att_w1 = (const float*)d_in[15];
    const float* att_w2 = (const float*)d_in[16];
    const float* a2_w1  = (const float*)d_in[17];
    const float* a2_b1  = (const float*)d_in[18];
    const float* a2_w2  = (const float*)d_in[19];
    const float* a2_b2  = (const float*)d_in[20];
    const float* curv   = (const float*)d_in[21];
    float* out = (float*)d_out;

    const int ag_smem = AGG_SMEM_FLOATS*4;
    const int ml_smem = ML_SMEM_FLOATS*4;
    cudaFuncSetAttribute(agg_kernel, cudaFuncAttributeMaxDynamicSharedMemorySize, ag_smem);
    cudaFuncSetAttribute(mlcl_gemm,  cudaFuncAttributeMaxDynamicSharedMemorySize, ml_smem);

    zero_kernel<<<(2*ROWS + 1023)/1024, 1024>>>();
    packw_kernel<<<32, 256>>>(att_w1, a2_w1);
    init_kernel<<<Bq, 256>>>(E, items, ucf_h, ukg_h, icf_h);

    dim3 gb(Bq, 2, 4);
    agg_kernel<<<gb, 256, ag_smem>>>(E, R,
        ucf_h, ucf_r, ucf_t, ikg_h, ikg_r, ikg_t,
        ukg_h, ukg_r, ukg_t, icf_h, icf_r, icf_t,
        att_w2, a2_b1, a2_w2, a2_b2, curv);

    dim3 gg(48, 96, 2);
    mlcl_gemm<<<gg, 256, ml_smem>>>();
    loss_kernel<<<2*ROWS/8, 256>>>();
    scores_kernel<<<Bq/8, 256>>>(out, out_size);
}

// round 14
// speedup vs baseline: 1.5113x; 1.5113x over previous
#include <cuda_runtime.h>
#include <math.h>

#define Bq 2048
#define Mq 64
#define Dq 64
#define BMq (Bq*Mq)
#define NPB (3*Bq*Dq)
#define ROWS 6144

// ---------------- device scratch ----------------
__device__ float g_embs[4*3*Bq*Dq];
__device__ float g_norm[4*3*Bq*Dq];
__device__ float g_rowsum[2*ROWS];
__device__ float g_colsum[2*ROWS];
__device__ float g_loss;

__device__ __forceinline__ unsigned cvt_tf32(float x){
    unsigned r; asm("cvt.rna.tf32.f32 %0, %1;" : "=r"(r) : "f"(x)); return r;
}
__device__ __forceinline__ float cvt_tf32f(float x){ return __uint_as_float(cvt_tf32(x)); }

__device__ __forceinline__ void mma_tf32(float* c, const unsigned* a, unsigned b0, unsigned b1){
    asm volatile(
        "mma.sync.aligned.m16n8k8.row.col.f32.tf32.tf32.f32 "
        "{%0,%1,%2,%3}, {%4,%5,%6,%7}, {%8,%9}, {%0,%1,%2,%3};"
        : "+f"(c[0]), "+f"(c[1]), "+f"(c[2]), "+f"(c[3])
        : "r"(a[0]), "r"(a[1]), "r"(a[2]), "r"(a[3]), "r"(b0), "r"(b1));
}

__device__ __forceinline__ float wsum(float v){
#pragma unroll
    for (int o = 16; o; o >>= 1) v += __shfl_xor_sync(0xffffffffu, v, o);
    return v;
}
__device__ __forceinline__ void wsum5(float &a, float &b, float &c, float &d, float &e){
#pragma unroll
    for (int o = 16; o; o >>= 1){
        a += __shfl_xor_sync(0xffffffffu, a, o);
        b += __shfl_xor_sync(0xffffffffu, b, o);
        c += __shfl_xor_sync(0xffffffffu, c, o);
        d += __shfl_xor_sync(0xffffffffu, d, o);
        e += __shfl_xor_sync(0xffffffffu, e, o);
    }
}
__device__ __forceinline__ float wmax(float v){
#pragma unroll
    for (int o = 16; o; o >>= 1) v = fmaxf(v, __shfl_xor_sync(0xffffffffu, v, o));
    return v;
}
__device__ __forceinline__ int eidx(int bl, int l, int b, int j){
    return (((bl*3 + l)*Bq) + b)*Dq + j;
}
__device__ __forceinline__ float ftanh(float x){
    float e = __expf(2.f*x);
    return 1.f - 2.f/(e + 1.f);
}
__device__ __forceinline__ float fartanh_clip(float x){
    x = fminf(fmaxf(x, -1.f + 1e-5f), 1.f - 1e-5f);
    return 0.5f*__logf((1.f + x)/(1.f - x));
}

// ---------------- zero accumulators ----------------
__global__ void zero_kernel(){
    int i = blockIdx.x*1024 + threadIdx.x;
    if (i < 2*ROWS){ g_rowsum[i] = 0.f; g_colsum[i] = 0.f; }
    if (i == 0) g_loss = 0.f;
}

// ---------------- init embeddings + fused normalize ----------------
__global__ __launch_bounds__(256) void init_kernel(
    const float* __restrict__ E, const int* __restrict__ items,
    const int* __restrict__ ucf_h, const int* __restrict__ ukg_h,
    const int* __restrict__ icf_h){
    __shared__ float pp[3][4][68];
    __shared__ float rows[4][68];
    __shared__ float inr[4];
    int b = blockIdx.x, tid = threadIdx.x;
    int j = tid & 63, q = tid >> 6;
    int lane = tid & 31, wid = tid >> 5;
    float s0 = 0.f, s2 = 0.f, s3 = 0.f;
#pragma unroll 4
    for (int mm = 0; mm < 16; ++mm){
        int m = q*16 + mm;
        s0 += E[ucf_h[b*Mq + m]*Dq + j];
        s2 += E[ukg_h[b*Mq + m]*Dq + j];
        s3 += E[icf_h[b*Mq + m]*Dq + j];
    }
    pp[0][q][j] = s0; pp[1][q][j] = s2; pp[2][q][j] = s3;
    __syncthreads();
    if (tid < 64){
        const float inv = 1.f/64.f;
        rows[0][tid] = (pp[0][0][tid]+pp[0][1][tid]+pp[0][2][tid]+pp[0][3][tid])*inv;
        rows[1][tid] = E[items[b]*Dq + tid];
        rows[2][tid] = (pp[1][0][tid]+pp[1][1][tid]+pp[1][2][tid]+pp[1][3][tid])*inv;
        rows[3][tid] = (pp[2][0][tid]+pp[2][1][tid]+pp[2][2][tid]+pp[2][3][tid])*inv;
    }
    __syncthreads();
    if (wid < 4){
        float v = rows[wid][lane]*rows[wid][lane] + rows[wid][lane+32]*rows[wid][lane+32];
        v = wsum(v);
        if (lane == 0) inr[wid] = 1.f/fmaxf(sqrtf(v), 1e-12f);
    }
    __syncthreads();
    if (tid < 64){
#pragma unroll
        for (int bl = 0; bl < 4; ++bl){
            float o = rows[bl][tid];
            g_embs[eidx(bl,0,b,tid)] = o;
            g_norm[eidx(bl,0,b,tid)] = o*inr[bl];
        }
    }
}

// ---------------- unified aggregation kernel (exact R9) ----------------
#define AGG_SMEM_FLOATS (64*132 + 64*68 + 64 + 64 + 4*68 + 64*3 + 16)

__device__ __forceinline__ void ed_body(
    float* sm, int b, int layer, int build,
    const float* __restrict__ E, const float* __restrict__ R,
    const int* __restrict__ hI, const int* __restrict__ rI, const int* __restrict__ tI,
    const float* __restrict__ W1, const float* __restrict__ W2)
{
    float* xs = sm;                     // [64][132] tf32
    float* ts = xs + 64*132;            // [64][68]
    float* av = ts + 64*68;             // [64]
    float* wv = av + 64;                // [64]
    float* pp = wv + 64;                // [4][68]

    const int tid = threadIdx.x, lane = tid & 31, wid = tid >> 5;
    const int gid = lane >> 2, tig = lane & 3;

    if (tid < 64) av[tid] = 0.f;

    for (int e = tid; e < 1024; e += 256){
        int m = e & 63, k4 = e >> 6;
        float4 hv = *(const float4*)&E[hI[b*Mq + m]*Dq + k4*4];
        float4 pv = *(const float4*)&R[rI[b*Mq + m]*Dq + k4*4];
        if (layer){
            float4 h2 = *(const float4*)&E[hI[BMq + b*Mq + m]*Dq + k4*4];
            hv.x += h2.x; hv.y += h2.y; hv.z += h2.z; hv.w += h2.w;
            float4 p2 = *(const float4*)&R[rI[BMq + b*Mq + m]*Dq + k4*4];
            pv.x *= p2.x; pv.y *= p2.y; pv.z *= p2.z; pv.w *= p2.w;
        }
        float4 tv = *(const float4*)&E[tI[layer*BMq + b*Mq + m]*Dq + k4*4];
        float4 hc = make_float4(cvt_tf32f(hv.x), cvt_tf32f(hv.y), cvt_tf32f(hv.z), cvt_tf32f(hv.w));
        float4 pc = make_float4(cvt_tf32f(pv.x), cvt_tf32f(pv.y), cvt_tf32f(pv.z), cvt_tf32f(pv.w));
        *(float4*)&xs[m*132 + k4*4]      = hc;
        *(float4*)&xs[m*132 + 64 + k4*4] = pc;
        *(float4*)&ts[m*68 + k4*4] = tv;
    }
    __syncthreads();

    {
        const int m0 = (wid & 1)*32, n0 = (wid >> 1)*16;
        float acc[2][2][4] = {};
#pragma unroll
        for (int kk = 0; kk < 16; ++kk){
            unsigned a[2][4];
#pragma unroll
            for (int mi = 0; mi < 2; ++mi){
                int base = (m0 + mi*16 + gid)*132 + kk*8 + tig;
                a[mi][0] = __float_as_uint(xs[base]);
                a[mi][1] = __float_as_uint(xs[base + 8*132]);
                a[mi][2] = __float_as_uint(xs[base + 4]);
                a[mi][3] = __float_as_uint(xs[base + 8*132 + 4]);
            }
            int kb = kk*8 + tig;
#pragma unroll
            for (int ni = 0; ni < 2; ++ni){
                int c = n0 + ni*8 + gid;
                unsigned b0 = cvt_tf32(__ldg(&W1[kb*64 + c]));
                unsigned b1 = cvt_tf32(__ldg(&W1[(kb+4)*64 + c]));
                mma_tf32(acc[0][ni], a[0], b0, b1);
                mma_tf32(acc[1][ni], a[1], b0, b1);
            }
        }
#pragma unroll
        for (int mi = 0; mi < 2; ++mi){
            float slo = 0.f, shi = 0.f;
#pragma unroll
            for (int ni = 0; ni < 2; ++ni){
                int c = n0 + ni*8 + tig*2;
                float w2a = __ldg(&W2[c]), w2b = __ldg(&W2[c+1]);
                slo += fmaxf(acc[mi][ni][0],0.f)*w2a + fmaxf(acc[mi][ni][1],0.f)*w2b;
                shi += fmaxf(acc[mi][ni][2],0.f)*w2a + fmaxf(acc[mi][ni][3],0.f)*w2b;
            }
            slo += __shfl_xor_sync(0xffffffffu, slo, 1);
            slo += __shfl_xor_sync(0xffffffffu, slo, 2);
            shi += __shfl_xor_sync(0xffffffffu, shi, 1);
            shi += __shfl_xor_sync(0xffffffffu, shi, 2);
            if (tig == 0){
                atomicAdd(&av[m0 + mi*16 + gid],     slo);
                atomicAdd(&av[m0 + mi*16 + gid + 8], shi);
            }
        }
    }
    __syncthreads();

    if (wid == 0){
        float a0 = 1.f/(1.f + __expf(-av[lane]));
        float a1 = 1.f/(1.f + __expf(-av[lane+32]));
        float mx = wmax(fmaxf(a0, a1));
        float e0 = __expf(a0 - mx), e1 = __expf(a1 - mx);
        float s = wsum(e0 + e1);
        wv[lane] = e0/s; wv[lane+32] = e1/s;
    }
    __syncthreads();

    {
        int j = tid & 63, q = tid >> 6;
        float o = 0.f;
#pragma unroll 4
        for (int mm = 0; mm < 16; ++mm){
            int m = q*16 + mm;
            o += wv[m]*ts[m*68 + j];
        }
        pp[q*68 + j] = o;
    }
    __syncthreads();
    if (tid < 64) av[tid] = pp[tid] + pp[68+tid] + pp[136+tid] + pp[204+tid];
    __syncthreads();
    if (wid == 0){
        float v = av[lane]*av[lane] + av[lane+32]*av[lane+32];
        v = wsum(v);
        if (lane == 0) wv[0] = 1.f/fmaxf(sqrtf(v), 1e-12f);
    }
    __syncthreads();
    if (tid < 64){
        float o = av[tid];
        g_embs[eidx(build, layer+1, b, tid)] = o;
        g_norm[eidx(build, layer+1, b, tid)] = o*wv[0];
    }
}

__device__ __forceinline__ void hyper_body(
    float* sm, int b, int layer, int build,
    const float* __restrict__ E, const float* __restrict__ R,
    const int* __restrict__ hI, const int* __restrict__ rI, const int* __restrict__ tI,
    const float* __restrict__ W1, const float* __restrict__ B1,
    const float* __restrict__ W2, const float* __restrict__ B2,
    const float* __restrict__ curv)
{
    float* tang = sm;                   // [64][132]
    float* hts  = tang + 64*132;        // [64][65] inside [64][68]
    float* av   = hts + 64*68;          // [64]
    float* wv   = av + 64;              // [64]
    float* pp   = wv + 64;              // [4][68]
    float* mp   = pp + 4*68;            // [64]
    float* ht2s = mp + 64;              // [64]
    float* istg = ht2s + 64;            // [64]
    float* scal = istg + 64;            // [16]

    const int tid = threadIdx.x, lane = tid & 31, wid = tid >> 5;
    const int gid = lane >> 2, tig = lane & 3;

    const float absc = fabsf(curv[0]);
    const float th1  = 0.761594155955765f;
    const float sh0  = th1*absc;
    const float hh2  = sh0*sh0;
    const float lam  = 2.f/fmaxf(1.f - hh2, 1e-15f);
    const float tyc  = ftanh(lam*0.5f);
    const float y2c  = tyc*tyc;
    const float c2c  = 1.f - hh2;

    if (tid < 64) av[tid] = 0.f;

    const float2* E2 = (const float2*)E;
    const float2* R2 = (const float2*)R;

#pragma unroll 2
    for (int r = 0; r < 8; ++r){
        int m = wid*8 + r;
        float2 h2v = E2[hI[b*Mq + m]*32 + lane];
        float2 p2v = R2[rI[b*Mq + m]*32 + lane];
        if (layer){
            float2 hB = E2[hI[BMq + b*Mq + m]*32 + lane];
            h2v.x += hB.x; h2v.y += hB.y;
            float2 pB = R2[rI[BMq + b*Mq + m]*32 + lane];
            p2v.x *= pB.x; p2v.y *= pB.y;
        }
        float2 t2v = E2[tI[layer*BMq + b*Mq + m]*32 + lane];
        float hv0 = h2v.x, hv1 = h2v.y;
        float pv0 = p2v.x, pv1 = p2v.y;
        float tv0 = t2v.x, tv1 = t2v.y;

        float nh2 = hv0*hv0 + hv1*hv1;
        float np2 = pv0*pv0 + pv1*pv1;
        float nt2 = tv0*tv0 + tv1*tv1;
        float dht = hv0*tv0 + hv1*tv1;
        float dhp = hv0*pv0 + hv1*pv1;
        wsum5(nh2, np2, nt2, dht, dhp);

        float ih = 1.f/fmaxf(sqrtf(nh2), 1e-12f);
        float ip = 1.f/fmaxf(sqrtf(np2), 1e-12f);
        float it = 1.f/fmaxf(sqrtf(nt2), 1e-12f);

        float sh = sh0*ih;
        float sy = tyc*it;
        float sq = tyc*ip;

        float xy = sh*sy*dht;
        float xq = sh*sq*dhp;

        float c1 = 1.f + 2.f*xy + y2c;
        float den = fmaxf(1.f + 2.f*xy + hh2*y2c, 1e-15f);
        float invden = 1.f/den;
        float ht0 = (c1*sh*hv0 + c2c*sy*tv0)*invden;
        float ht1 = (c1*sh*hv1 + c2c*sy*tv1)*invden;
        float ht2 = (c1*c1*hh2 + 2.f*c1*c2c*xy + c2c*c2c*y2c)*invden*invden;

        float d1 = 1.f + 2.f*xq + y2c;
        float dd = fmaxf(1.f + 2.f*xq + hh2*y2c, 1e-15f);
        float invdd = 1.f/dd;
        float hr0 = (d1*sh*hv0 + c2c*sq*pv0)*invdd;
        float hr1 = (d1*sh*hv1 + c2c*sq*pv1)*invdd;
        float hr2 = (d1*d1*hh2 + 2.f*d1*c2c*xq + c2c*c2c*y2c)*invdd*invdd;

        float n128 = sqrtf(fmaxf(hh2 + hr2, 1e-15f));
        float stg = fartanh_clip(n128)/n128;

        hts[m*65 + 2*lane] = ht0; hts[m*65 + 2*lane + 1] = ht1;
        if (lane == 0){ ht2s[m] = ht2; istg[m] = 1.f/stg; }
        *(float2*)&tang[m*132 + 2*lane]      = make_float2(stg*sh*hv0, stg*sh*hv1);
        *(float2*)&tang[m*132 + 64 + 2*lane] = make_float2(stg*hr0,    stg*hr1);
    }
    __syncthreads();

    // phase 2: MLP via tf32 mma
    {
        const int m0 = (wid & 1)*32, n0 = (wid >> 1)*16;
        float acc[2][2][4] = {};
#pragma unroll
        for (int kk = 0; kk < 16; ++kk){
            unsigned a[2][4];
#pragma unroll
            for (int mi = 0; mi < 2; ++mi){
                int base = (m0 + mi*16 + gid)*132 + kk*8 + tig;
                a[mi][0] = cvt_tf32(tang[base]);
                a[mi][1] = cvt_tf32(tang[base + 8*132]);
                a[mi][2] = cvt_tf32(tang[base + 4]);
                a[mi][3] = cvt_tf32(tang[base + 8*132 + 4]);
            }
            int kb = kk*8 + tig;
#pragma unroll
            for (int ni = 0; ni < 2; ++ni){
                int c = n0 + ni*8 + gid;
                unsigned b0 = cvt_tf32(__ldg(&W1[kb*64 + c]));
                unsigned b1 = cvt_tf32(__ldg(&W1[(kb+4)*64 + c]));
                mma_tf32(acc[0][ni], a[0], b0, b1);
                mma_tf32(acc[1][ni], a[1], b0, b1);
            }
        }
#pragma unroll
        for (int mi = 0; mi < 2; ++mi){
            float slo = 0.f, shi = 0.f;
#pragma unroll
            for (int ni = 0; ni < 2; ++ni){
                int c = n0 + ni*8 + tig*2;
                float w2a = __ldg(&W2[c]), w2b = __ldg(&W2[c+1]);
                float b1a = __ldg(&B1[c]), b1b = __ldg(&B1[c+1]);
                slo += fmaxf(acc[mi][ni][0] + b1a, 0.f)*w2a + fmaxf(acc[mi][ni][1] + b1b, 0.f)*w2b;
                shi += fmaxf(acc[mi][ni][2] + b1a, 0.f)*w2a + fmaxf(acc[mi][ni][3] + b1b, 0.f)*w2b;
            }
            slo += __shfl_xor_sync(0xffffffffu, slo, 1);
            slo += __shfl_xor_sync(0xffffffffu, slo, 2);
            shi += __shfl_xor_sync(0xffffffffu, shi, 1);
            shi += __shfl_xor_sync(0xffffffffu, shi, 2);
            if (tig == 0){
                atomicAdd(&av[m0 + mi*16 + gid],     slo);
                atomicAdd(&av[m0 + mi*16 + gid + 8], shi);
            }
        }
    }
    __syncthreads();

    if (wid == 0){
        const float b2 = B2[0];
        float a0 = ftanh(av[lane] + b2);
        float a1 = ftanh(av[lane+32] + b2);
        float mx = wmax(fmaxf(a0, a1));
        float e0 = __expf(a0 - mx), e1 = __expf(a1 - mx);
        float s = wsum(e0 + e1);
        wv[lane] = e0/s; wv[lane+32] = e1/s;
    }
    __syncthreads();

    // phase 3
    if (tid < 64) av[tid] = wv[tid]*istg[tid];
    __syncthreads();
    {
        int j = tid & 63, q = tid >> 6;
        float a = 0.f;
#pragma unroll 4
        for (int mm = 0; mm < 16; ++mm){
            int m = q*16 + mm;
            a += av[m]*tang[m*132 + j];
        }
        pp[q*68 + j] = a;
    }
    __syncthreads();
    if (tid < 64) mp[tid] = pp[tid] + pp[68+tid] + pp[136+tid] + pp[204+tid];
    __syncthreads();
    if (wid == 0){
        float v = mp[lane]*mp[lane] + mp[lane+32]*mp[lane+32];
        v = wsum(v);
        if (lane == 0) scal[0] = v;
    }
    __syncthreads();
    {
        int m = tid & 63, q = tid >> 6;
        float a = 0.f;
#pragma unroll 4
        for (int jj = 0; jj < 16; ++jj){
            int j = q*16 + jj;
            a += hts[m*65 + j]*mp[j];
        }
        pp[q*68 + m] = a;
    }
    __syncthreads();
    if (tid < 64){
        float dsum = pp[tid] + pp[68+tid] + pp[136+tid] + pp[204+tid];
        float p2v = scal[0];
        float wm = wv[tid];
        float xy = -wm*dsum;
        float y2 = wm*wm*ht2s[tid];
        float c2v = 1.f - p2v;
        float c1v = 1.f + 2.f*xy + y2;
        float den = fmaxf(1.f + 2.f*xy + p2v*y2, 1e-15f);
        float invden = 1.f/den;
        float n2 = (c1v*c1v*p2v + 2.f*c1v*c2v*xy + c2v*c2v*y2)*invden*invden;
        float n = sqrtf(fmaxf(n2, 1e-15f));
        float lamp = 2.f/fmaxf(1.f - p2v, 1e-15f);
        float sc = (2.f/lamp)*fartanh_clip(n)/n;
        av[tid]   = wm*sc*c1v*invden;    // alv
        istg[tid] = wm*wm*sc*c2v*invden; // bev
    }
    __syncthreads();
    if (wid == 0){
        float sa = av[lane] + av[lane+32];
        sa = wsum(sa);
        if (lane == 0) scal[1] = sa;
    }
    __syncthreads();
    {
        int j = tid & 63, q = tid >> 6;
        float o = 0.f;
#pragma unroll 4
        for (int mm = 0; mm < 16; ++mm){
            int m = q*16 + mm;
            o += istg[m]*hts[m*65 + j];
        }
        pp[q*68 + j] = o;
    }
    __syncthreads();
    if (tid < 64)
        ht2s[tid] = (pp[tid] + pp[68+tid] + pp[136+tid] + pp[204+tid]) - mp[tid]*scal[1];
    __syncthreads();
    if (wid == 0){
        float v = ht2s[lane]*ht2s[lane] + ht2s[lane+32]*ht2s[lane+32];
        v = wsum(v);
        if (lane == 0) scal[2] = 1.f/fmaxf(sqrtf(v), 1e-12f);
    }
    __syncthreads();
    if (tid < 64){
        float o = ht2s[tid];
        g_embs[eidx(build, layer+1, b, tid)] = o;
        g_norm[eidx(build, layer+1, b, tid)] = o*scal[2];
    }
}

__global__ __launch_bounds__(256) void agg_kernel(
    const float* __restrict__ E, const float* __restrict__ R,
    const int* __restrict__ ucf_h, const int* __restrict__ ucf_r, const int* __restrict__ ucf_t,
    const int* __restrict__ ikg_h, const int* __restrict__ ikg_r, const int* __restrict__ ikg_t,
    const int* __restrict__ ukg_h, const int* __restrict__ ukg_r, const int* __restrict__ ukg_t,
    const int* __restrict__ icf_h, const int* __restrict__ icf_r, const int* __restrict__ icf_t,
    const float* __restrict__ att_w1, const float* __restrict__ att_w2,
    const float* __restrict__ a2_w1, const float* __restrict__ a2_b1,
    const float* __restrict__ a2_w2, const float* __restrict__ a2_b2,
    const float* __restrict__ curv)
{
    extern __shared__ float sm[];
    const int b = blockIdx.x, layer = blockIdx.y, z = blockIdx.z;
    if (z == 0)      ed_body(sm, b, layer, 0, E, R, ucf_h, ucf_r, ucf_t, att_w1, att_w2);
    else if (z == 1) ed_body(sm, b, layer, 1, E, R, ikg_h, ikg_r, ikg_t, att_w1, att_w2);
    else if (z == 2) hyper_body(sm, b, layer, 2, E, R, ukg_h, ukg_r, ukg_t, a2_w1, a2_b1, a2_w2, a2_b2, curv);
    else             hyper_body(sm, b, layer, 3, E, R, icf_h, icf_r, icf_t, a2_w1, a2_b1, a2_w2, a2_b2, curv);
}

// ---------------- MLCL GEMM: 64x128 tiles, coalesced staging, scalar frags ----------------
#define ML_SMEM_FLOATS (64*68 + 128*68 + 64 + 128)
__global__ __launch_bounds__(256) void mlcl_gemm(){
    const int pair = blockIdx.z;
    const float* A  = g_norm + (pair == 0 ? 0 : 1)*NPB;
    const float* Bn = g_norm + (pair == 0 ? 2 : 3)*NPB;
    float* rs = g_rowsum + pair*ROWS;
    float* cs = g_colsum + pair*ROWS;

    extern __shared__ float sm[];
    float* As = sm;                 // [64][68] tf32
    float* Bs = As + 64*68;         // [128][68] tf32
    float* rowpart = Bs + 128*68;   // [64]
    float* colpart = rowpart + 64;  // [128]

    const int tid = threadIdx.x;
    const int by = blockIdx.y, bx = blockIdx.x;
    const int lane = tid & 31, wid = tid >> 5;
    const int gid = lane >> 2, tig = lane & 3;

    for (int e = tid; e < 1024; e += 256){
        int i = e >> 4, k4 = e & 15;
        float4 v = *(const float4*)&A[(by*64 + i)*64 + k4*4];
        *(float4*)&As[i*68 + k4*4] =
            make_float4(cvt_tf32f(v.x), cvt_tf32f(v.y), cvt_tf32f(v.z), cvt_tf32f(v.w));
    }
    for (int e = tid; e < 2048; e += 256){
        int i = e >> 4, k4 = e & 15;
        float4 v = *(const float4*)&Bn[(bx*128 + i)*64 + k4*4];
        *(float4*)&Bs[i*68 + k4*4] =
            make_float4(cvt_tf32f(v.x), cvt_tf32f(v.y), cvt_tf32f(v.z), cvt_tf32f(v.w));
    }
    if (tid < 64) rowpart[tid] = 0.f;
    if (tid < 128) colpart[tid] = 0.f;
    __syncthreads();

    const int m0 = (wid & 3)*16, n0 = (wid >> 2)*64;
    float acc[8][4] = {};
#pragma unroll
    for (int kk = 0; kk < 8; ++kk){
        int abase = (m0 + gid)*68 + kk*8 + tig;
        unsigned a[4] = { __float_as_uint(As[abase]),
                          __float_as_uint(As[abase + 8*68]),
                          __float_as_uint(As[abase + 4]),
                          __float_as_uint(As[abase + 8*68 + 4]) };
#pragma unroll
        for (int ni = 0; ni < 8; ++ni){
            int bb = (n0 + ni*8 + gid)*68 + kk*8 + tig;
            mma_tf32(acc[ni], a, __float_as_uint(Bs[bb]), __float_as_uint(Bs[bb + 4]));
        }
    }

    float cl[8], ch[8];
#pragma unroll
    for (int ni = 0; ni < 8; ++ni){ cl[ni] = 0.f; ch[ni] = 0.f; }
    float rlo = 0.f, rhi = 0.f;
#pragma unroll
    for (int ni = 0; ni < 8; ++ni){
        float e0 = __expf(5.f*acc[ni][0]);
        float e1 = __expf(5.f*acc[ni][1]);
        float e2 = __expf(5.f*acc[ni][2]);
        float e3 = __expf(5.f*acc[ni][3]);
        rlo += e0 + e1; rhi += e2 + e3;
        cl[ni] += e0 + e2; ch[ni] += e1 + e3;
    }
    rlo += __shfl_xor_sync(0xffffffffu, rlo, 1);
    rlo += __shfl_xor_sync(0xffffffffu, rlo, 2);
    rhi += __shfl_xor_sync(0xffffffffu, rhi, 1);
    rhi += __shfl_xor_sync(0xffffffffu, rhi, 2);
    if (tig == 0){
        atomicAdd(&rowpart[m0 + gid],     rlo);
        atomicAdd(&rowpart[m0 + gid + 8], rhi);
    }
#pragma unroll
    for (int ni = 0; ni < 8; ++ni){
        cl[ni] += __shfl_xor_sync(0xffffffffu, cl[ni], 4);
        cl[ni] += __shfl_xor_sync(0xffffffffu, cl[ni], 8);
        cl[ni] += __shfl_xor_sync(0xffffffffu, cl[ni], 16);
        ch[ni] += __shfl_xor_sync(0xffffffffu, ch[ni], 4);
        ch[ni] += __shfl_xor_sync(0xffffffffu, ch[ni], 8);
        ch[ni] += __shfl_xor_sync(0xffffffffu, ch[ni], 16);
        if (gid == 0){
            atomicAdd(&colpart[n0 + ni*8 + tig*2],     cl[ni]);
            atomicAdd(&colpart[n0 + ni*8 + tig*2 + 1], ch[ni]);
        }
    }
    __syncthreads();
    if (tid < 64)  atomicAdd(&rs[by*64  + tid], rowpart[tid]);
    if (tid < 128) atomicAdd(&cs[bx*128 + tid], colpart[tid]);
}

// ---------------- loss reduction ----------------
__global__ void loss_kernel(){
    const int wid = threadIdx.x >> 5, lane = threadIdx.x & 31;
    int r = blockIdx.x*8 + wid;
    int pair = r >= ROWS;
    int i = r - pair*ROWS;
    const float* A  = g_norm + (pair ? 1 : 0)*NPB;
    const float* Bn = g_norm + (pair ? 3 : 2)*NPB;
    float d = A[i*64 + lane]*Bn[i*64 + lane] + A[i*64 + lane + 32]*Bn[i*64 + lane + 32];
    d = wsum(d);
    __shared__ float red[8];
    if (lane == 0)
        red[wid] = logf(g_rowsum[pair*ROWS + i]) + logf(g_colsum[pair*ROWS + i]) - 10.f*d;
    __syncthreads();
    if (threadIdx.x == 0){
        float s = 0.f;
#pragma unroll
        for (int w = 0; w < 8; ++w) s += red[w];
        atomicAdd(&g_loss, s);
    }
}

// ---------------- scores + loss finalize ----------------
__global__ void scores_kernel(float* out, int out_size){
    int b = blockIdx.x*8 + (threadIdx.x >> 5);
    int lane = threadIdx.x & 31;
    if (blockIdx.x == 0 && threadIdx.x == 0 && out_size > Bq) out[Bq] = 1e-6f*g_loss;
    if (b >= Bq) return;
    float s = 0.f;
#pragma unroll
    for (int l = 0; l < 3; ++l){
        s += g_embs[eidx(0,l,b,lane)]   *g_embs[eidx(3,l,b,lane)]
           + g_embs[eidx(0,l,b,lane+32)]*g_embs[eidx(3,l,b,lane+32)]
           + g_embs[eidx(2,l,b,lane)]   *g_embs[eidx(1,l,b,lane)]
           + g_embs[eidx(2,l,b,lane+32)]*g_embs[eidx(1,l,b,lane+32)];
    }
    s = wsum(s);
    if (lane == 0) out[b] = 1.f/(1.f + expf(-s));
}

// ---------------- launch ----------------
extern "C" void kernel_launch(void* const* d_in, const int* in_sizes, int n_in,
                              void* d_out, int out_size){
    (void)in_sizes; (void)n_in;
    const int*   items  = (const int*)  d_in[0];
    const int*   ucf_h  = (const int*)  d_in[1];
    const int*   ucf_r  = (const int*)  d_in[2];
    const int*   ucf_t  = (const int*)  d_in[3];
    const int*   ikg_h  = (const int*)  d_in[4];
    const int*   ikg_r  = (const int*)  d_in[5];
    const int*   ikg_t  = (const int*)  d_in[6];
    const int*   ukg_h  = (const int*)  d_in[7];
    const int*   ukg_r  = (const int*)  d_in[8];
    const int*   ukg_t  = (const int*)  d_in[9];
    const int*   icf_h  = (const int*)  d_in[10];
    const int*   icf_r  = (const int*)  d_in[11];
    const int*   icf_t  = (const int*)  d_in[12];
    const float* E      = (const float*)d_in[13];
    const float* R      = (const float*)d_in[14];
    const float* att_w1 = (const float*)d_in[15];
    const float* att_w2 = (const float*)d_in[16];
    const float* a2_w1  = (const float*)d_in[17];
    const float* a2_b1  = (const float*)d_in[18];
    const float* a2_w2  = (const float*)d_in[19];
    const float* a2_b2  = (const float*)d_in[20];
    const float* curv   = (const float*)d_in[21];
    float* out = (float*)d_out;

    const int ag_smem = AGG_SMEM_FLOATS*4;
    const int ml_smem = ML_SMEM_FLOATS*4;
    cudaFuncSetAttribute(agg_kernel, cudaFuncAttributeMaxDynamicSharedMemorySize, ag_smem);
    cudaFuncSetAttribute(mlcl_gemm,  cudaFuncAttributeMaxDynamicSharedMemorySize, ml_smem);

    zero_kernel<<<(2*ROWS + 1023)/1024, 1024>>>();
    init_kernel<<<Bq, 256>>>(E, items, ucf_h, ukg_h, icf_h);

    dim3 gb(Bq, 2, 4);
    agg_kernel<<<gb, 256, ag_smem>>>(E, R,
        ucf_h, ucf_r, ucf_t, ikg_h, ikg_r, ikg_t,
        ukg_h, ukg_r, ukg_t, icf_h, icf_r, icf_t,
        att_w1, att_w2, a2_w1, a2_b1, a2_w2, a2_b2, curv);

    dim3 gg(48, 96, 2);
    mlcl_gemm<<<gg, 256, ml_smem>>>();
    loss_kernel<<<2*ROWS/8, 256>>>();
    scores_kernel<<<Bq/8, 256>>>(out, out_size);
}

// round 15
// speedup vs baseline: 1.5485x; 1.0246x over previous
#include <cuda_runtime.h>
#include <math.h>

#define Bq 2048
#define Mq 64
#define Dq 64
#define BMq (Bq*Mq)
#define NPB (3*Bq*Dq)
#define ROWS 6144

// ---------------- device scratch ----------------
__device__ float g_embs[4*3*Bq*Dq];
__device__ float g_norm[4*3*Bq*Dq];
__device__ float g_rowsum[2*ROWS];
__device__ float g_colsum[2*ROWS];
__device__ float g_loss;

__device__ __forceinline__ unsigned cvt_tf32(float x){
    unsigned r; asm("cvt.rna.tf32.f32 %0, %1;" : "=r"(r) : "f"(x)); return r;
}
__device__ __forceinline__ float cvt_tf32f(float x){ return __uint_as_float(cvt_tf32(x)); }

__device__ __forceinline__ void mma_tf32(float* c, const unsigned* a, unsigned b0, unsigned b1){
    asm volatile(
        "mma.sync.aligned.m16n8k8.row.col.f32.tf32.tf32.f32 "
        "{%0,%1,%2,%3}, {%4,%5,%6,%7}, {%8,%9}, {%0,%1,%2,%3};"
        : "+f"(c[0]), "+f"(c[1]), "+f"(c[2]), "+f"(c[3])
        : "r"(a[0]), "r"(a[1]), "r"(a[2]), "r"(a[3]), "r"(b0), "r"(b1));
}

__device__ __forceinline__ float wsum(float v){
#pragma unroll
    for (int o = 16; o; o >>= 1) v += __shfl_xor_sync(0xffffffffu, v, o);
    return v;
}
__device__ __forceinline__ void wsum10(float* v){
#pragma unroll
    for (int o = 16; o; o >>= 1){
#pragma unroll
        for (int i = 0; i < 10; ++i) v[i] += __shfl_xor_sync(0xffffffffu, v[i], o);
    }
}
__device__ __forceinline__ float wmax(float v){
#pragma unroll
    for (int o = 16; o; o >>= 1) v = fmaxf(v, __shfl_xor_sync(0xffffffffu, v, o));
    return v;
}
__device__ __forceinline__ int eidx(int bl, int l, int b, int j){
    return (((bl*3 + l)*Bq) + b)*Dq + j;
}
__device__ __forceinline__ float ftanh(float x){
    float e = __expf(2.f*x);
    return 1.f - 2.f/(e + 1.f);
}
__device__ __forceinline__ float fartanh_clip(float x){
    x = fminf(fmaxf(x, -1.f + 1e-5f), 1.f - 1e-5f);
    return 0.5f*__logf((1.f + x)/(1.f - x));
}

// ---------------- zero accumulators ----------------
__global__ void zero_kernel(){
    int i = blockIdx.x*1024 + threadIdx.x;
    if (i < 2*ROWS){ g_rowsum[i] = 0.f; g_colsum[i] = 0.f; }
    if (i == 0) g_loss = 0.f;
}

// ---------------- init embeddings + fused normalize ----------------
__global__ __launch_bounds__(256) void init_kernel(
    const float* __restrict__ E, const int* __restrict__ items,
    const int* __restrict__ ucf_h, const int* __restrict__ ukg_h,
    const int* __restrict__ icf_h){
    __shared__ float pp[3][4][68];
    __shared__ float rows[4][68];
    __shared__ float inr[4];
    int b = blockIdx.x, tid = threadIdx.x;
    int j = tid & 63, q = tid >> 6;
    int lane = tid & 31, wid = tid >> 5;
    float s0 = 0.f, s2 = 0.f, s3 = 0.f;
#pragma unroll 4
    for (int mm = 0; mm < 16; ++mm){
        int m = q*16 + mm;
        s0 += E[ucf_h[b*Mq + m]*Dq + j];
        s2 += E[ukg_h[b*Mq + m]*Dq + j];
        s3 += E[icf_h[b*Mq + m]*Dq + j];
    }
    pp[0][q][j] = s0; pp[1][q][j] = s2; pp[2][q][j] = s3;
    __syncthreads();
    if (tid < 64){
        const float inv = 1.f/64.f;
        rows[0][tid] = (pp[0][0][tid]+pp[0][1][tid]+pp[0][2][tid]+pp[0][3][tid])*inv;
        rows[1][tid] = E[items[b]*Dq + tid];
        rows[2][tid] = (pp[1][0][tid]+pp[1][1][tid]+pp[1][2][tid]+pp[1][3][tid])*inv;
        rows[3][tid] = (pp[2][0][tid]+pp[2][1][tid]+pp[2][2][tid]+pp[2][3][tid])*inv;
    }
    __syncthreads();
    if (wid < 4){
        float v = rows[wid][lane]*rows[wid][lane] + rows[wid][lane+32]*rows[wid][lane+32];
        v = wsum(v);
        if (lane == 0) inr[wid] = 1.f/fmaxf(sqrtf(v), 1e-12f);
    }
    __syncthreads();
    if (tid < 64){
#pragma unroll
        for (int bl = 0; bl < 4; ++bl){
            float o = rows[bl][tid];
            g_embs[eidx(bl,0,b,tid)] = o;
            g_norm[eidx(bl,0,b,tid)] = o*inr[bl];
        }
    }
}

// ---------------- unified aggregation kernel ----------------
#define AGG_SMEM_FLOATS (64*132 + 64*68 + 64 + 64 + 4*68 + 64*3 + 16)

__device__ __forceinline__ void ed_body(
    float* sm, int b, int layer, int build,
    const float* __restrict__ E, const float* __restrict__ R,
    const int* __restrict__ hI, const int* __restrict__ rI, const int* __restrict__ tI,
    const float* __restrict__ W1, const float* __restrict__ W2)
{
    float* xs = sm;                     // [64][132] tf32
    float* ts = xs + 64*132;            // [64][68]
    float* av = ts + 64*68;             // [64]
    float* wv = av + 64;                // [64]
    float* pp = wv + 64;                // [4][68]

    const int tid = threadIdx.x, lane = tid & 31, wid = tid >> 5;
    const int gid = lane >> 2, tig = lane & 3;

    if (tid < 64) av[tid] = 0.f;

    for (int e = tid; e < 1024; e += 256){
        int m = e & 63, k4 = e >> 6;
        float4 hv = *(const float4*)&E[hI[b*Mq + m]*Dq + k4*4];
        float4 pv = *(const float4*)&R[rI[b*Mq + m]*Dq + k4*4];
        if (layer){
            float4 h2 = *(const float4*)&E[hI[BMq + b*Mq + m]*Dq + k4*4];
            hv.x += h2.x; hv.y += h2.y; hv.z += h2.z; hv.w += h2.w;
            float4 p2 = *(const float4*)&R[rI[BMq + b*Mq + m]*Dq + k4*4];
            pv.x *= p2.x; pv.y *= p2.y; pv.z *= p2.z; pv.w *= p2.w;
        }
        float4 tv = *(const float4*)&E[tI[layer*BMq + b*Mq + m]*Dq + k4*4];
        float4 hc = make_float4(cvt_tf32f(hv.x), cvt_tf32f(hv.y), cvt_tf32f(hv.z), cvt_tf32f(hv.w));
        float4 pc = make_float4(cvt_tf32f(pv.x), cvt_tf32f(pv.y), cvt_tf32f(pv.z), cvt_tf32f(pv.w));
        *(float4*)&xs[m*132 + k4*4]      = hc;
        *(float4*)&xs[m*132 + 64 + k4*4] = pc;
        *(float4*)&ts[m*68 + k4*4] = tv;
    }
    __syncthreads();

    {
        const int m0 = (wid & 1)*32, n0 = (wid >> 1)*16;
        float acc[2][2][4] = {};
#pragma unroll
        for (int kk = 0; kk < 16; ++kk){
            unsigned a[2][4];
#pragma unroll
            for (int mi = 0; mi < 2; ++mi){
                int base = (m0 + mi*16 + gid)*132 + kk*8 + tig;
                a[mi][0] = __float_as_uint(xs[base]);
                a[mi][1] = __float_as_uint(xs[base + 8*132]);
                a[mi][2] = __float_as_uint(xs[base + 4]);
                a[mi][3] = __float_as_uint(xs[base + 8*132 + 4]);
            }
            int kb = kk*8 + tig;
#pragma unroll
            for (int ni = 0; ni < 2; ++ni){
                int c = n0 + ni*8 + gid;
                unsigned b0 = cvt_tf32(__ldg(&W1[kb*64 + c]));
                unsigned b1 = cvt_tf32(__ldg(&W1[(kb+4)*64 + c]));
                mma_tf32(acc[0][ni], a[0], b0, b1);
                mma_tf32(acc[1][ni], a[1], b0, b1);
            }
        }
#pragma unroll
        for (int mi = 0; mi < 2; ++mi){
            float slo = 0.f, shi = 0.f;
#pragma unroll
            for (int ni = 0; ni < 2; ++ni){
                int c = n0 + ni*8 + tig*2;
                float w2a = __ldg(&W2[c]), w2b = __ldg(&W2[c+1]);
                slo += fmaxf(acc[mi][ni][0],0.f)*w2a + fmaxf(acc[mi][ni][1],0.f)*w2b;
                shi += fmaxf(acc[mi][ni][2],0.f)*w2a + fmaxf(acc[mi][ni][3],0.f)*w2b;
            }
            slo += __shfl_xor_sync(0xffffffffu, slo, 1);
            slo += __shfl_xor_sync(0xffffffffu, slo, 2);
            shi += __shfl_xor_sync(0xffffffffu, shi, 1);
            shi += __shfl_xor_sync(0xffffffffu, shi, 2);
            if (tig == 0){
                atomicAdd(&av[m0 + mi*16 + gid],     slo);
                atomicAdd(&av[m0 + mi*16 + gid + 8], shi);
            }
        }
    }
    __syncthreads();

    if (wid == 0){
        float a0 = 1.f/(1.f + __expf(-av[lane]));
        float a1 = 1.f/(1.f + __expf(-av[lane+32]));
        float mx = wmax(fmaxf(a0, a1));
        float e0 = __expf(a0 - mx), e1 = __expf(a1 - mx);
        float s = wsum(e0 + e1);
        wv[lane] = e0/s; wv[lane+32] = e1/s;
    }
    __syncthreads();

    {
        int j = tid & 63, q = tid >> 6;
        float o = 0.f;
#pragma unroll 4
        for (int mm = 0; mm < 16; ++mm){
            int m = q*16 + mm;
            o += wv[m]*ts[m*68 + j];
        }
        pp[q*68 + j] = o;
    }
    __syncthreads();
    if (tid < 64) av[tid] = pp[tid] + pp[68+tid] + pp[136+tid] + pp[204+tid];
    __syncthreads();
    if (wid == 0){
        float v = av[lane]*av[lane] + av[lane+32]*av[lane+32];
        v = wsum(v);
        if (lane == 0) wv[0] = 1.f/fmaxf(sqrtf(v), 1e-12f);
    }
    __syncthreads();
    if (tid < 64){
        float o = av[tid];
        g_embs[eidx(build, layer+1, b, tid)] = o;
        g_norm[eidx(build, layer+1, b, tid)] = o*wv[0];
    }
}

__device__ __forceinline__ void hyper_body(
    float* sm, int b, int layer, int build,
    const float* __restrict__ E, const float* __restrict__ R,
    const int* __restrict__ hI, const int* __restrict__ rI, const int* __restrict__ tI,
    const float* __restrict__ W1, const float* __restrict__ B1,
    const float* __restrict__ W2, const float* __restrict__ B2,
    const float* __restrict__ curv)
{
    float* tang = sm;                   // [64][132]
    float* hts  = tang + 64*132;        // [64][65] inside [64][68]
    float* av   = hts + 64*68;          // [64]
    float* wv   = av + 64;              // [64]
    float* pp   = wv + 64;              // [4][68]
    float* mp   = pp + 4*68;            // [64]
    float* ht2s = mp + 64;              // [64]
    float* istg = ht2s + 64;            // [64]
    float* scal = istg + 64;            // [16]

    const int tid = threadIdx.x, lane = tid & 31, wid = tid >> 5;
    const int gid = lane >> 2, tig = lane & 3;

    const float absc = fabsf(curv[0]);
    const float th1  = 0.761594155955765f;
    const float sh0  = th1*absc;
    const float hh2  = sh0*sh0;
    const float lam  = 2.f/fmaxf(1.f - hh2, 1e-15f);
    const float tyc  = ftanh(lam*0.5f);
    const float y2c  = tyc*tyc;
    const float c2c  = 1.f - hh2;

    if (tid < 64) av[tid] = 0.f;

    const float2* E2 = (const float2*)E;
    const float2* R2 = (const float2*)R;

    // ---- phase 1: TWO rows per iteration, fused 10-wide reduction ----
    for (int r = 0; r < 8; r += 2){
        int ma = wid*8 + r, mb = ma + 1;

        float2 hA = E2[hI[b*Mq + ma]*32 + lane];
        float2 pA = R2[rI[b*Mq + ma]*32 + lane];
        float2 hB = E2[hI[b*Mq + mb]*32 + lane];
        float2 pB = R2[rI[b*Mq + mb]*32 + lane];
        if (layer){
            float2 h2 = E2[hI[BMq + b*Mq + ma]*32 + lane];
            hA.x += h2.x; hA.y += h2.y;
            float2 p2 = R2[rI[BMq + b*Mq + ma]*32 + lane];
            pA.x *= p2.x; pA.y *= p2.y;
            float2 h3 = E2[hI[BMq + b*Mq + mb]*32 + lane];
            hB.x += h3.x; hB.y += h3.y;
            float2 p3 = R2[rI[BMq + b*Mq + mb]*32 + lane];
            pB.x *= p3.x; pB.y *= p3.y;
        }
        float2 tA = E2[tI[layer*BMq + b*Mq + ma]*32 + lane];
        float2 tB = E2[tI[layer*BMq + b*Mq + mb]*32 + lane];

        float red[10];
        red[0] = hA.x*hA.x + hA.y*hA.y;   // nh2 a
        red[1] = pA.x*pA.x + pA.y*pA.y;   // np2 a
        red[2] = tA.x*tA.x + tA.y*tA.y;   // nt2 a
        red[3] = hA.x*tA.x + hA.y*tA.y;   // dht a
        red[4] = hA.x*pA.x + hA.y*pA.y;   // dhp a
        red[5] = hB.x*hB.x + hB.y*hB.y;
        red[6] = pB.x*pB.x + pB.y*pB.y;
        red[7] = tB.x*tB.x + tB.y*tB.y;
        red[8] = hB.x*tB.x + hB.y*tB.y;
        red[9] = hB.x*pB.x + hB.y*pB.y;
        wsum10(red);

#pragma unroll
        for (int s = 0; s < 2; ++s){
            int m = s ? mb : ma;
            float hv0 = s ? hB.x : hA.x, hv1 = s ? hB.y : hA.y;
            float pv0 = s ? pB.x : pA.x, pv1 = s ? pB.y : pA.y;
            float tv0 = s ? tB.x : tA.x, tv1 = s ? tB.y : tA.y;
            float nh2 = red[s*5+0], np2 = red[s*5+1], nt2 = red[s*5+2];
            float dht = red[s*5+3], dhp = red[s*5+4];

            float ih = 1.f/fmaxf(sqrtf(nh2), 1e-12f);
            float ip = 1.f/fmaxf(sqrtf(np2), 1e-12f);
            float it = 1.f/fmaxf(sqrtf(nt2), 1e-12f);

            float sh = sh0*ih;
            float sy = tyc*it;
            float sq = tyc*ip;

            float xy = sh*sy*dht;
            float xq = sh*sq*dhp;

            float c1 = 1.f + 2.f*xy + y2c;
            float den = fmaxf(1.f + 2.f*xy + hh2*y2c, 1e-15f);
            float invden = 1.f/den;
            float ht0 = (c1*sh*hv0 + c2c*sy*tv0)*invden;
            float ht1 = (c1*sh*hv1 + c2c*sy*tv1)*invden;
            float ht2 = (c1*c1*hh2 + 2.f*c1*c2c*xy + c2c*c2c*y2c)*invden*invden;

            float d1 = 1.f + 2.f*xq + y2c;
            float dd = fmaxf(1.f + 2.f*xq + hh2*y2c, 1e-15f);
            float invdd = 1.f/dd;
            float hr0 = (d1*sh*hv0 + c2c*sq*pv0)*invdd;
            float hr1 = (d1*sh*hv1 + c2c*sq*pv1)*invdd;
            float hr2 = (d1*d1*hh2 + 2.f*d1*c2c*xq + c2c*c2c*y2c)*invdd*invdd;

            float n128 = sqrtf(fmaxf(hh2 + hr2, 1e-15f));
            float stg = fartanh_clip(n128)/n128;

            hts[m*65 + 2*lane] = ht0; hts[m*65 + 2*lane + 1] = ht1;
            if (lane == 0){ ht2s[m] = ht2; istg[m] = 1.f/stg; }
            *(float2*)&tang[m*132 + 2*lane]      = make_float2(stg*sh*hv0, stg*sh*hv1);
            *(float2*)&tang[m*132 + 64 + 2*lane] = make_float2(stg*hr0,    stg*hr1);
        }
    }
    __syncthreads();

    // phase 2: MLP via tf32 mma
    {
        const int m0 = (wid & 1)*32, n0 = (wid >> 1)*16;
        float acc[2][2][4] = {};
#pragma unroll
        for (int kk = 0; kk < 16; ++kk){
            unsigned a[2][4];
#pragma unroll
            for (int mi = 0; mi < 2; ++mi){
                int base = (m0 + mi*16 + gid)*132 + kk*8 + tig;
                a[mi][0] = cvt_tf32(tang[base]);
                a[mi][1] = cvt_tf32(tang[base + 8*132]);
                a[mi][2] = cvt_tf32(tang[base + 4]);
                a[mi][3] = cvt_tf32(tang[base + 8*132 + 4]);
            }
            int kb = kk*8 + tig;
#pragma unroll
            for (int ni = 0; ni < 2; ++ni){
                int c = n0 + ni*8 + gid;
                unsigned b0 = cvt_tf32(__ldg(&W1[kb*64 + c]));
                unsigned b1 = cvt_tf32(__ldg(&W1[(kb+4)*64 + c]));
                mma_tf32(acc[0][ni], a[0], b0, b1);
                mma_tf32(acc[1][ni], a[1], b0, b1);
            }
        }
#pragma unroll
        for (int mi = 0; mi < 2; ++mi){
            float slo = 0.f, shi = 0.f;
#pragma unroll
            for (int ni = 0; ni < 2; ++ni){
                int c = n0 + ni*8 + tig*2;
                float w2a = __ldg(&W2[c]), w2b = __ldg(&W2[c+1]);
                float b1a = __ldg(&B1[c]), b1b = __ldg(&B1[c+1]);
                slo += fmaxf(acc[mi][ni][0] + b1a, 0.f)*w2a + fmaxf(acc[mi][ni][1] + b1b, 0.f)*w2b;
                shi += fmaxf(acc[mi][ni][2] + b1a, 0.f)*w2a + fmaxf(acc[mi][ni][3] + b1b, 0.f)*w2b;
            }
            slo += __shfl_xor_sync(0xffffffffu, slo, 1);
            slo += __shfl_xor_sync(0xffffffffu, slo, 2);
            shi += __shfl_xor_sync(0xffffffffu, shi, 1);
            shi += __shfl_xor_sync(0xffffffffu, shi, 2);
            if (tig == 0){
                atomicAdd(&av[m0 + mi*16 + gid],     slo);
                atomicAdd(&av[m0 + mi*16 + gid + 8], shi);
            }
        }
    }
    __syncthreads();

    if (wid == 0){
        const float b2 = B2[0];
        float a0 = ftanh(av[lane] + b2);
        float a1 = ftanh(av[lane+32] + b2);
        float mx = wmax(fmaxf(a0, a1));
        float e0 = __expf(a0 - mx), e1 = __expf(a1 - mx);
        float s = wsum(e0 + e1);
        wv[lane] = e0/s; wv[lane+32] = e1/s;
    }
    __syncthreads();

    // phase 3
    if (tid < 64) av[tid] = wv[tid]*istg[tid];
    __syncthreads();
    {
        int j = tid & 63, q = tid >> 6;
        float a = 0.f;
#pragma unroll 4
        for (int mm = 0; mm < 16; ++mm){
            int m = q*16 + mm;
            a += av[m]*tang[m*132 + j];
        }
        pp[q*68 + j] = a;
    }
    __syncthreads();
    if (tid < 64) mp[tid] = pp[tid] + pp[68+tid] + pp[136+tid] + pp[204+tid];
    __syncthreads();
    if (wid == 0){
        float v = mp[lane]*mp[lane] + mp[lane+32]*mp[lane+32];
        v = wsum(v);
        if (lane == 0) scal[0] = v;
    }
    __syncthreads();
    {
        int m = tid & 63, q = tid >> 6;
        float a = 0.f;
#pragma unroll 4
        for (int jj = 0; jj < 16; ++jj){
            int j = q*16 + jj;
            a += hts[m*65 + j]*mp[j];
        }
        pp[q*68 + m] = a;
    }
    __syncthreads();
    if (tid < 64){
        float dsum = pp[tid] + pp[68+tid] + pp[136+tid] + pp[204+tid];
        float p2v = scal[0];
        float wm = wv[tid];
        float xy = -wm*dsum;
        float y2 = wm*wm*ht2s[tid];
        float c2v = 1.f - p2v;
        float c1v = 1.f + 2.f*xy + y2;
        float den = fmaxf(1.f + 2.f*xy + p2v*y2, 1e-15f);
        float invden = 1.f/den;
        float n2 = (c1v*c1v*p2v + 2.f*c1v*c2v*xy + c2v*c2v*y2)*invden*invden;
        float n = sqrtf(fmaxf(n2, 1e-15f));
        float lamp = 2.f/fmaxf(1.f - p2v, 1e-15f);
        float sc = (2.f/lamp)*fartanh_clip(n)/n;
        av[tid]   = wm*sc*c1v*invden;    // alv
        istg[tid] = wm*wm*sc*c2v*invden; // bev
    }
    __syncthreads();
    if (wid == 0){
        float sa = av[lane] + av[lane+32];
        sa = wsum(sa);
        if (lane == 0) scal[1] = sa;
    }
    __syncthreads();
    {
        int j = tid & 63, q = tid >> 6;
        float o = 0.f;
#pragma unroll 4
        for (int mm = 0; mm < 16; ++mm){
            int m = q*16 + mm;
            o += istg[m]*hts[m*65 + j];
        }
        pp[q*68 + j] = o;
    }
    __syncthreads();
    if (tid < 64)
        ht2s[tid] = (pp[tid] + pp[68+tid] + pp[136+tid] + pp[204+tid]) - mp[tid]*scal[1];
    __syncthreads();
    if (wid == 0){
        float v = ht2s[lane]*ht2s[lane] + ht2s[lane+32]*ht2s[lane+32];
        v = wsum(v);
        if (lane == 0) scal[2] = 1.f/fmaxf(sqrtf(v), 1e-12f);
    }
    __syncthreads();
    if (tid < 64){
        float o = ht2s[tid];
        g_embs[eidx(build, layer+1, b, tid)] = o;
        g_norm[eidx(build, layer+1, b, tid)] = o*scal[2];
    }
}

__global__ __launch_bounds__(256) void agg_kernel(
    const float* __restrict__ E, const float* __restrict__ R,
    const int* __restrict__ ucf_h, const int* __restrict__ ucf_r, const int* __restrict__ ucf_t,
    const int* __restrict__ ikg_h, const int* __restrict__ ikg_r, const int* __restrict__ ikg_t,
    const int* __restrict__ ukg_h, const int* __restrict__ ukg_r, const int* __restrict__ ukg_t,
    const int* __restrict__ icf_h, const int* __restrict__ icf_r, const int* __restrict__ icf_t,
    const float* __restrict__ att_w1, const float* __restrict__ att_w2,
    const float* __restrict__ a2_w1, const float* __restrict__ a2_b1,
    const float* __restrict__ a2_w2, const float* __restrict__ a2_b2,
    const float* __restrict__ curv)
{
    extern __shared__ float sm[];
    const int b = blockIdx.x, layer = blockIdx.y, z = blockIdx.z;
    if (z == 0)      ed_body(sm, b, layer, 0, E, R, ucf_h, ucf_r, ucf_t, att_w1, att_w2);
    else if (z == 1) ed_body(sm, b, layer, 1, E, R, ikg_h, ikg_r, ikg_t, att_w1, att_w2);
    else if (z == 2) hyper_body(sm, b, layer, 2, E, R, ukg_h, ukg_r, ukg_t, a2_w1, a2_b1, a2_w2, a2_b2, curv);
    else             hyper_body(sm, b, layer, 3, E, R, icf_h, icf_r, icf_t, a2_w1, a2_b1, a2_w2, a2_b2, curv);
}

// ---------------- MLCL GEMM: R9 128x128 tiles ----------------
#define ML_SMEM_FLOATS (128*68*2 + 256)
__global__ __launch_bounds__(256) void mlcl_gemm(){
    const int pair = blockIdx.z;
    const float* A  = g_norm + (pair == 0 ? 0 : 1)*NPB;
    const float* Bn = g_norm + (pair == 0 ? 2 : 3)*NPB;
    float* rs = g_rowsum + pair*ROWS;
    float* cs = g_colsum + pair*ROWS;

    extern __shared__ float sm[];
    float* As = sm;                 // [128][68] tf32
    float* Bs = As + 128*68;        // [128][68] tf32
    float* rowpart = Bs + 128*68;   // [128]
    float* colpart = rowpart + 128; // [128]

    const int tid = threadIdx.x;
    const int by = blockIdx.y, bx = blockIdx.x;
    const int lane = tid & 31, wid = tid >> 5;
    const int gid = lane >> 2, tig = lane & 3;

    for (int e = tid; e < 2048; e += 256){
        int i = e >> 4, k4 = e & 15;
        float4 v = *(const float4*)&A[(by*128 + i)*64 + k4*4];
        *(float4*)&As[i*68 + k4*4] =
            make_float4(cvt_tf32f(v.x), cvt_tf32f(v.y), cvt_tf32f(v.z), cvt_tf32f(v.w));
        float4 w = *(const float4*)&Bn[(bx*128 + i)*64 + k4*4];
        *(float4*)&Bs[i*68 + k4*4] =
            make_float4(cvt_tf32f(w.x), cvt_tf32f(w.y), cvt_tf32f(w.z), cvt_tf32f(w.w));
    }
    if (tid < 128){ rowpart[tid] = 0.f; colpart[tid] = 0.f; }
    __syncthreads();

    const int m0 = (wid & 3)*32, n0 = (wid >> 2)*64;
    float acc[2][8][4] = {};
#pragma unroll
    for (int kk = 0; kk < 8; ++kk){
        unsigned a[2][4];
#pragma unroll
        for (int mi = 0; mi < 2; ++mi){
            int base = (m0 + mi*16 + gid)*68 + kk*8 + tig;
            a[mi][0] = __float_as_uint(As[base]);
            a[mi][1] = __float_as_uint(As[base + 8*68]);
            a[mi][2] = __float_as_uint(As[base + 4]);
            a[mi][3] = __float_as_uint(As[base + 8*68 + 4]);
        }
#pragma unroll
        for (int ni = 0; ni < 8; ++ni){
            int bb = (n0 + ni*8 + gid)*68 + kk*8 + tig;
            unsigned b0 = __float_as_uint(Bs[bb]);
            unsigned b1 = __float_as_uint(Bs[bb + 4]);
            mma_tf32(acc[0][ni], a[0], b0, b1);
            mma_tf32(acc[1][ni], a[1], b0, b1);
        }
    }

    float cl[8], ch[8];
#pragma unroll
    for (int ni = 0; ni < 8; ++ni){ cl[ni] = 0.f; ch[ni] = 0.f; }
#pragma unroll
    for (int mi = 0; mi < 2; ++mi){
        float rlo = 0.f, rhi = 0.f;
#pragma unroll
        for (int ni = 0; ni < 8; ++ni){
            float e0 = __expf(5.f*acc[mi][ni][0]);
            float e1 = __expf(5.f*acc[mi][ni][1]);
            float e2 = __expf(5.f*acc[mi][ni][2]);
            float e3 = __expf(5.f*acc[mi][ni][3]);
            rlo += e0 + e1; rhi += e2 + e3;
            cl[ni] += e0 + e2; ch[ni] += e1 + e3;
        }
        rlo += __shfl_xor_sync(0xffffffffu, rlo, 1);
        rlo += __shfl_xor_sync(0xffffffffu, rlo, 2);
        rhi += __shfl_xor_sync(0xffffffffu, rhi, 1);
        rhi += __shfl_xor_sync(0xffffffffu, rhi, 2);
        if (tig == 0){
            atomicAdd(&rowpart[m0 + mi*16 + gid],     rlo);
            atomicAdd(&rowpart[m0 + mi*16 + gid + 8], rhi);
        }
    }
#pragma unroll
    for (int ni = 0; ni < 8; ++ni){
        cl[ni] += __shfl_xor_sync(0xffffffffu, cl[ni], 4);
        cl[ni] += __shfl_xor_sync(0xffffffffu, cl[ni], 8);
        cl[ni] += __shfl_xor_sync(0xffffffffu, cl[ni], 16);
        ch[ni] += __shfl_xor_sync(0xffffffffu, ch[ni], 4);
        ch[ni] += __shfl_xor_sync(0xffffffffu, ch[ni], 8);
        ch[ni] += __shfl_xor_sync(0xffffffffu, ch[ni], 16);
        if (gid == 0){
            atomicAdd(&colpart[n0 + ni*8 + tig*2],     cl[ni]);
            atomicAdd(&colpart[n0 + ni*8 + tig*2 + 1], ch[ni]);
        }
    }
    __syncthreads();
    if (tid < 128){
        atomicAdd(&rs[by*128 + tid], rowpart[tid]);
        atomicAdd(&cs[bx*128 + tid], colpart[tid]);
    }
}

// ---------------- loss reduction ----------------
__global__ void loss_kernel(){
    const int wid = threadIdx.x >> 5, lane = threadIdx.x & 31;
    int r = blockIdx.x*8 + wid;
    int pair = r >= ROWS;
    int i = r - pair*ROWS;
    const float* A  = g_norm + (pair ? 1 : 0)*NPB;
    const float* Bn = g_norm + (pair ? 3 : 2)*NPB;
    float d = A[i*64 + lane]*Bn[i*64 + lane] + A[i*64 + lane + 32]*Bn[i*64 + lane + 32];
    d = wsum(d);
    __shared__ float red[8];
    if (lane == 0)
        red[wid] = logf(g_rowsum[pair*ROWS + i]) + logf(g_colsum[pair*ROWS + i]) - 10.f*d;
    __syncthreads();
    if (threadIdx.x == 0){
        float s = 0.f;
#pragma unroll
        for (int w = 0; w < 8; ++w) s += red[w];
        atomicAdd(&g_loss, s);
    }
}

// ---------------- scores + loss finalize ----------------
__global__ void scores_kernel(float* out, int out_size){
    int b = blockIdx.x*8 + (threadIdx.x >> 5);
    int lane = threadIdx.x & 31;
    if (blockIdx.x == 0 && threadIdx.x == 0 && out_size > Bq) out[Bq] = 1e-6f*g_loss;
    if (b >= Bq) return;
    float s = 0.f;
#pragma unroll
    for (int l = 0; l < 3; ++l){
        s += g_embs[eidx(0,l,b,lane)]   *g_embs[eidx(3,l,b,lane)]
           + g_embs[eidx(0,l,b,lane+32)]*g_embs[eidx(3,l,b,lane+32)]
           + g_embs[eidx(2,l,b,lane)]   *g_embs[eidx(1,l,b,lane)]
           + g_embs[eidx(2,l,b,lane+32)]*g_embs[eidx(1,l,b,lane+32)];
    }
    s = wsum(s);
    if (lane == 0) out[b] = 1.f/(1.f + expf(-s));
}

// ---------------- launch ----------------
extern "C" void kernel_launch(void* const* d_in, const int* in_sizes, int n_in,
                              void* d_out, int out_size){
    (void)in_sizes; (void)n_in;
    const int*   items  = (const int*)  d_in[0];
    const int*   ucf_h  = (const int*)  d_in[1];
    const int*   ucf_r  = (const int*)  d_in[2];
    const int*   ucf_t  = (const int*)  d_in[3];
    const int*   ikg_h  = (const int*)  d_in[4];
    const int*   ikg_r  = (const int*)  d_in[5];
    const int*   ikg_t  = (const int*)  d_in[6];
    const int*   ukg_h  = (const int*)  d_in[7];
    const int*   ukg_r  = (const int*)  d_in[8];
    const int*   ukg_t  = (const int*)  d_in[9];
    const int*   icf_h  = (const int*)  d_in[10];
    const int*   icf_r  = (const int*)  d_in[11];
    const int*   icf_t  = (const int*)  d_in[12];
    const float* E      = (const float*)d_in[13];
    const float* R      = (const float*)d_in[14];
    const float* att_w1 = (const float*)d_in[15];
    const float* att_w2 = (const float*)d_in[16];
    const float* a2_w1  = (const float*)d_in[17];
    const float* a2_b1  = (const float*)d_in[18];
    const float* a2_w2  = (const float*)d_in[19];
    const float* a2_b2  = (const float*)d_in[20];
    const float* curv   = (const float*)d_in[21];
    float* out = (float*)d_out;

    const int ag_smem = AGG_SMEM_FLOATS*4;
    const int ml_smem = ML_SMEM_FLOATS*4;
    cudaFuncSetAttribute(agg_kernel, cudaFuncAttributeMaxDynamicSharedMemorySize, ag_smem);
    cudaFuncSetAttribute(mlcl_gemm,  cudaFuncAttributeMaxDynamicSharedMemorySize, ml_smem);

    zero_kernel<<<(2*ROWS + 1023)/1024, 1024>>>();
    init_kernel<<<Bq, 256>>>(E, items, ucf_h, ukg_h, icf_h);

    dim3 gb(Bq, 2, 4);
    agg_kernel<<<gb, 256, ag_smem>>>(E, R,
        ucf_h, ucf_r, ucf_t, ikg_h, ikg_r, ikg_t,
        ukg_h, ukg_r, ukg_t, icf_h, icf_r, icf_t,
        att_w1, att_w2, a2_w1, a2_b1, a2_w2, a2_b2, curv);

    dim3 gg(48, 48, 2);
    mlcl_gemm<<<gg, 256, ml_smem>>>();
    loss_kernel<<<2*ROWS/8, 256>>>();
    scores_kernel<<<Bq/8, 256>>>(out, out_size);
}

// round 16
// speedup vs baseline: 1.6393x; 1.0586x over previous
#include <cuda_runtime.h>
#include <math.h>

#define Bq 2048
#define Mq 64
#define Dq 64
#define BMq (Bq*Mq)
#define NPB (3*Bq*Dq)
#define ROWS 6144

// ---------------- device scratch ----------------
__device__ float g_embs[4*3*Bq*Dq];
__device__ float g_norm[4*3*Bq*Dq];
__device__ float g_rowsum[2*ROWS];
__device__ float g_colsum[2*ROWS];
__device__ float g_loss;

__device__ __forceinline__ unsigned cvt_tf32(float x){
    unsigned r; asm("cvt.rna.tf32.f32 %0, %1;" : "=r"(r) : "f"(x)); return r;
}
__device__ __forceinline__ float cvt_tf32f(float x){ return __uint_as_float(cvt_tf32(x)); }

__device__ __forceinline__ void mma_tf32(float* c, const unsigned* a, unsigned b0, unsigned b1){
    asm volatile(
        "mma.sync.aligned.m16n8k8.row.col.f32.tf32.tf32.f32 "
        "{%0,%1,%2,%3}, {%4,%5,%6,%7}, {%8,%9}, {%0,%1,%2,%3};"
        : "+f"(c[0]), "+f"(c[1]), "+f"(c[2]), "+f"(c[3])
        : "r"(a[0]), "r"(a[1]), "r"(a[2]), "r"(a[3]), "r"(b0), "r"(b1));
}

__device__ __forceinline__ float wsum(float v){
#pragma unroll
    for (int o = 16; o; o >>= 1) v += __shfl_xor_sync(0xffffffffu, v, o);
    return v;
}
__device__ __forceinline__ void wsum10(float* v){
#pragma unroll
    for (int o = 16; o; o >>= 1){
#pragma unroll
        for (int i = 0; i < 10; ++i) v[i] += __shfl_xor_sync(0xffffffffu, v[i], o);
    }
}
__device__ __forceinline__ float wmax(float v){
#pragma unroll
    for (int o = 16; o; o >>= 1) v = fmaxf(v, __shfl_xor_sync(0xffffffffu, v, o));
    return v;
}
__device__ __forceinline__ int eidx(int bl, int l, int b, int j){
    return (((bl*3 + l)*Bq) + b)*Dq + j;
}
__device__ __forceinline__ float ftanh(float x){
    float e = __expf(2.f*x);
    return 1.f - 2.f/(e + 1.f);
}
__device__ __forceinline__ float fartanh_clip(float x){
    x = fminf(fmaxf(x, -1.f + 1e-5f), 1.f - 1e-5f);
    return 0.5f*__logf((1.f + x)/(1.f - x));
}

// ---------------- zero accumulators ----------------
__global__ void zero_kernel(){
    int i = blockIdx.x*1024 + threadIdx.x;
    if (i < 2*ROWS){ g_rowsum[i] = 0.f; g_colsum[i] = 0.f; }
    if (i == 0) g_loss = 0.f;
}

// ---------------- init embeddings + fused normalize ----------------
__global__ __launch_bounds__(256) void init_kernel(
    const float* __restrict__ E, const int* __restrict__ items,
    const int* __restrict__ ucf_h, const int* __restrict__ ukg_h,
    const int* __restrict__ icf_h){
    __shared__ float pp[3][4][68];
    __shared__ float rows[4][68];
    __shared__ float inr[4];
    int b = blockIdx.x, tid = threadIdx.x;
    int j = tid & 63, q = tid >> 6;
    int lane = tid & 31, wid = tid >> 5;
    float s0 = 0.f, s2 = 0.f, s3 = 0.f;
#pragma unroll 4
    for (int mm = 0; mm < 16; ++mm){
        int m = q*16 + mm;
        s0 += E[ucf_h[b*Mq + m]*Dq + j];
        s2 += E[ukg_h[b*Mq + m]*Dq + j];
        s3 += E[icf_h[b*Mq + m]*Dq + j];
    }
    pp[0][q][j] = s0; pp[1][q][j] = s2; pp[2][q][j] = s3;
    __syncthreads();
    if (tid < 64){
        const float inv = 1.f/64.f;
        rows[0][tid] = (pp[0][0][tid]+pp[0][1][tid]+pp[0][2][tid]+pp[0][3][tid])*inv;
        rows[1][tid] = E[items[b]*Dq + tid];
        rows[2][tid] = (pp[1][0][tid]+pp[1][1][tid]+pp[1][2][tid]+pp[1][3][tid])*inv;
        rows[3][tid] = (pp[2][0][tid]+pp[2][1][tid]+pp[2][2][tid]+pp[2][3][tid])*inv;
    }
    __syncthreads();
    if (wid < 4){
        float v = rows[wid][lane]*rows[wid][lane] + rows[wid][lane+32]*rows[wid][lane+32];
        v = wsum(v);
        if (lane == 0) inr[wid] = 1.f/fmaxf(sqrtf(v), 1e-12f);
    }
    __syncthreads();
    if (tid < 64){
#pragma unroll
        for (int bl = 0; bl < 4; ++bl){
            float o = rows[bl][tid];
            g_embs[eidx(bl,0,b,tid)] = o;
            g_norm[eidx(bl,0,b,tid)] = o*inr[bl];
        }
    }
}

// ---------------- ed kernel (no ts -> 35.4KB smem -> 6 CTAs/SM) ----------------
#define ED_SMEM_FLOATS (64*132 + 64 + 64 + 4*68)
__global__ __launch_bounds__(256) void ed_kernel(
    const float* __restrict__ E, const float* __restrict__ R,
    const int* __restrict__ h0, const int* __restrict__ r0, const int* __restrict__ t0,
    const int* __restrict__ h1, const int* __restrict__ r1, const int* __restrict__ t1,
    const float* __restrict__ W1, const float* __restrict__ W2)
{
    extern __shared__ float sm[];
    float* xs = sm;                     // [64][132] tf32
    float* av = xs + 64*132;            // [64]
    float* wv = av + 64;                // [64]
    float* pp = wv + 64;                // [4][68]

    const int b = blockIdx.x, layer = blockIdx.y, buildz = blockIdx.z;
    const int* hI = buildz ? h1 : h0;
    const int* rI = buildz ? r1 : r0;
    const int* tI = buildz ? t1 : t0;
    const int build = buildz;
    const int tid = threadIdx.x, lane = tid & 31, wid = tid >> 5;
    const int gid = lane >> 2, tig = lane & 3;

    if (tid < 64) av[tid] = 0.f;

    for (int e = tid; e < 1024; e += 256){
        int m = e & 63, k4 = e >> 6;
        float4 hv = *(const float4*)&E[hI[b*Mq + m]*Dq + k4*4];
        float4 pv = *(const float4*)&R[rI[b*Mq + m]*Dq + k4*4];
        if (layer){
            float4 h2 = *(const float4*)&E[hI[BMq + b*Mq + m]*Dq + k4*4];
            hv.x += h2.x; hv.y += h2.y; hv.z += h2.z; hv.w += h2.w;
            float4 p2 = *(const float4*)&R[rI[BMq + b*Mq + m]*Dq + k4*4];
            pv.x *= p2.x; pv.y *= p2.y; pv.z *= p2.z; pv.w *= p2.w;
        }
        float4 hc = make_float4(cvt_tf32f(hv.x), cvt_tf32f(hv.y), cvt_tf32f(hv.z), cvt_tf32f(hv.w));
        float4 pc = make_float4(cvt_tf32f(pv.x), cvt_tf32f(pv.y), cvt_tf32f(pv.z), cvt_tf32f(pv.w));
        *(float4*)&xs[m*132 + k4*4]      = hc;
        *(float4*)&xs[m*132 + 64 + k4*4] = pc;
    }
    __syncthreads();

    {
        const int m0 = (wid & 1)*32, n0 = (wid >> 1)*16;
        float acc[2][2][4] = {};
#pragma unroll
        for (int kk = 0; kk < 16; ++kk){
            unsigned a[2][4];
#pragma unroll
            for (int mi = 0; mi < 2; ++mi){
                int base = (m0 + mi*16 + gid)*132 + kk*8 + tig;
                a[mi][0] = __float_as_uint(xs[base]);
                a[mi][1] = __float_as_uint(xs[base + 8*132]);
                a[mi][2] = __float_as_uint(xs[base + 4]);
                a[mi][3] = __float_as_uint(xs[base + 8*132 + 4]);
            }
            int kb = kk*8 + tig;
#pragma unroll
            for (int ni = 0; ni < 2; ++ni){
                int c = n0 + ni*8 + gid;
                unsigned b0 = cvt_tf32(__ldg(&W1[kb*64 + c]));
                unsigned b1 = cvt_tf32(__ldg(&W1[(kb+4)*64 + c]));
                mma_tf32(acc[0][ni], a[0], b0, b1);
                mma_tf32(acc[1][ni], a[1], b0, b1);
            }
        }
#pragma unroll
        for (int mi = 0; mi < 2; ++mi){
            float slo = 0.f, shi = 0.f;
#pragma unroll
            for (int ni = 0; ni < 2; ++ni){
                int c = n0 + ni*8 + tig*2;
                float w2a = __ldg(&W2[c]), w2b = __ldg(&W2[c+1]);
                slo += fmaxf(acc[mi][ni][0],0.f)*w2a + fmaxf(acc[mi][ni][1],0.f)*w2b;
                shi += fmaxf(acc[mi][ni][2],0.f)*w2a + fmaxf(acc[mi][ni][3],0.f)*w2b;
            }
            slo += __shfl_xor_sync(0xffffffffu, slo, 1);
            slo += __shfl_xor_sync(0xffffffffu, slo, 2);
            shi += __shfl_xor_sync(0xffffffffu, shi, 1);
            shi += __shfl_xor_sync(0xffffffffu, shi, 2);
            if (tig == 0){
                atomicAdd(&av[m0 + mi*16 + gid],     slo);
                atomicAdd(&av[m0 + mi*16 + gid + 8], shi);
            }
        }
    }
    __syncthreads();

    if (wid == 0){
        float a0 = 1.f/(1.f + __expf(-av[lane]));
        float a1 = 1.f/(1.f + __expf(-av[lane+32]));
        float mx = wmax(fmaxf(a0, a1));
        float e0 = __expf(a0 - mx), e1 = __expf(a1 - mx);
        float s = wsum(e0 + e1);
        wv[lane] = e0/s; wv[lane+32] = e1/s;
    }
    __syncthreads();

    // epilogue: out[j] = sum_m wv[m]*t[m][j], t reloaded from gmem (L1/L2-hot)
    {
        int j = tid & 63, q = tid >> 6;
        float o = 0.f;
#pragma unroll 4
        for (int mm = 0; mm < 16; ++mm){
            int m = q*16 + mm;
            o += wv[m]*__ldg(&E[tI[layer*BMq + b*Mq + m]*Dq + j]);
        }
        pp[q*68 + j] = o;
    }
    __syncthreads();
    if (tid < 64) av[tid] = pp[tid] + pp[68+tid] + pp[136+tid] + pp[204+tid];
    __syncthreads();
    if (wid == 0){
        float v = av[lane]*av[lane] + av[lane+32]*av[lane+32];
        v = wsum(v);
        if (lane == 0) wv[0] = 1.f/fmaxf(sqrtf(v), 1e-12f);
    }
    __syncthreads();
    if (tid < 64){
        float o = av[tid];
        g_embs[eidx(build, layer+1, b, tid)] = o;
        g_norm[eidx(build, layer+1, b, tid)] = o*wv[0];
    }
}

// ---------------- hyper kernel (R15 body) ----------------
#define HY_SMEM_FLOATS (64*132 + 64*68 + 64 + 64 + 4*68 + 64*3 + 16)
__global__ __launch_bounds__(256) void hyper_kernel(
    const float* __restrict__ E, const float* __restrict__ R,
    const int* __restrict__ h0, const int* __restrict__ r0, const int* __restrict__ t0,
    const int* __restrict__ h1, const int* __restrict__ r1, const int* __restrict__ t1,
    const float* __restrict__ W1, const float* __restrict__ B1,
    const float* __restrict__ W2, const float* __restrict__ B2,
    const float* __restrict__ curv)
{
    extern __shared__ float sm[];
    float* tang = sm;                   // [64][132]
    float* hts  = tang + 64*132;        // [64][65] inside [64][68]
    float* av   = hts + 64*68;          // [64]
    float* wv   = av + 64;              // [64]
    float* pp   = wv + 64;              // [4][68]
    float* mp   = pp + 4*68;            // [64]
    float* ht2s = mp + 64;              // [64]
    float* istg = ht2s + 64;            // [64]
    float* scal = istg + 64;            // [16]

    const int b = blockIdx.x, layer = blockIdx.y, buildz = blockIdx.z;
    const int* hI = buildz ? h1 : h0;
    const int* rI = buildz ? r1 : r0;
    const int* tI = buildz ? t1 : t0;
    const int build = 2 + buildz;
    const int tid = threadIdx.x, lane = tid & 31, wid = tid >> 5;
    const int gid = lane >> 2, tig = lane & 3;

    const float absc = fabsf(curv[0]);
    const float th1  = 0.761594155955765f;
    const float sh0  = th1*absc;
    const float hh2  = sh0*sh0;
    const float lam  = 2.f/fmaxf(1.f - hh2, 1e-15f);
    const float tyc  = ftanh(lam*0.5f);
    const float y2c  = tyc*tyc;
    const float c2c  = 1.f - hh2;

    if (tid < 64) av[tid] = 0.f;

    const float2* E2 = (const float2*)E;
    const float2* R2 = (const float2*)R;

    for (int r = 0; r < 8; r += 2){
        int ma = wid*8 + r, mb = ma + 1;

        float2 hA = E2[hI[b*Mq + ma]*32 + lane];
        float2 pA = R2[rI[b*Mq + ma]*32 + lane];
        float2 hB = E2[hI[b*Mq + mb]*32 + lane];
        float2 pB = R2[rI[b*Mq + mb]*32 + lane];
        if (layer){
            float2 h2 = E2[hI[BMq + b*Mq + ma]*32 + lane];
            hA.x += h2.x; hA.y += h2.y;
            float2 p2 = R2[rI[BMq + b*Mq + ma]*32 + lane];
            pA.x *= p2.x; pA.y *= p2.y;
            float2 h3 = E2[hI[BMq + b*Mq + mb]*32 + lane];
            hB.x += h3.x; hB.y += h3.y;
            float2 p3 = R2[rI[BMq + b*Mq + mb]*32 + lane];
            pB.x *= p3.x; pB.y *= p3.y;
        }
        float2 tA = E2[tI[layer*BMq + b*Mq + ma]*32 + lane];
        float2 tB = E2[tI[layer*BMq + b*Mq + mb]*32 + lane];

        float red[10];
        red[0] = hA.x*hA.x + hA.y*hA.y;
        red[1] = pA.x*pA.x + pA.y*pA.y;
        red[2] = tA.x*tA.x + tA.y*tA.y;
        red[3] = hA.x*tA.x + hA.y*tA.y;
        red[4] = hA.x*pA.x + hA.y*pA.y;
        red[5] = hB.x*hB.x + hB.y*hB.y;
        red[6] = pB.x*pB.x + pB.y*pB.y;
        red[7] = tB.x*tB.x + tB.y*tB.y;
        red[8] = hB.x*tB.x + hB.y*tB.y;
        red[9] = hB.x*pB.x + hB.y*pB.y;
        wsum10(red);

#pragma unroll
        for (int s = 0; s < 2; ++s){
            int m = s ? mb : ma;
            float hv0 = s ? hB.x : hA.x, hv1 = s ? hB.y : hA.y;
            float pv0 = s ? pB.x : pA.x, pv1 = s ? pB.y : pA.y;
            float tv0 = s ? tB.x : tA.x, tv1 = s ? tB.y : tA.y;
            float nh2 = red[s*5+0], np2 = red[s*5+1], nt2 = red[s*5+2];
            float dht = red[s*5+3], dhp = red[s*5+4];

            float ih = 1.f/fmaxf(sqrtf(nh2), 1e-12f);
            float ip = 1.f/fmaxf(sqrtf(np2), 1e-12f);
            float it = 1.f/fmaxf(sqrtf(nt2), 1e-12f);

            float sh = sh0*ih;
            float sy = tyc*it;
            float sq = tyc*ip;

            float xy = sh*sy*dht;
            float xq = sh*sq*dhp;

            float c1 = 1.f + 2.f*xy + y2c;
            float den = fmaxf(1.f + 2.f*xy + hh2*y2c, 1e-15f);
            float invden = 1.f/den;
            float ht0 = (c1*sh*hv0 + c2c*sy*tv0)*invden;
            float ht1 = (c1*sh*hv1 + c2c*sy*tv1)*invden;
            float ht2 = (c1*c1*hh2 + 2.f*c1*c2c*xy + c2c*c2c*y2c)*invden*invden;

            float d1 = 1.f + 2.f*xq + y2c;
            float dd = fmaxf(1.f + 2.f*xq + hh2*y2c, 1e-15f);
            float invdd = 1.f/dd;
            float hr0 = (d1*sh*hv0 + c2c*sq*pv0)*invdd;
            float hr1 = (d1*sh*hv1 + c2c*sq*pv1)*invdd;
            float hr2 = (d1*d1*hh2 + 2.f*d1*c2c*xq + c2c*c2c*y2c)*invdd*invdd;

            float n128 = sqrtf(fmaxf(hh2 + hr2, 1e-15f));
            float stg = fartanh_clip(n128)/n128;

            hts[m*65 + 2*lane] = ht0; hts[m*65 + 2*lane + 1] = ht1;
            if (lane == 0){ ht2s[m] = ht2; istg[m] = 1.f/stg; }
            *(float2*)&tang[m*132 + 2*lane]      = make_float2(stg*sh*hv0, stg*sh*hv1);
            *(float2*)&tang[m*132 + 64 + 2*lane] = make_float2(stg*hr0,    stg*hr1);
        }
    }
    __syncthreads();

    {
        const int m0 = (wid & 1)*32, n0 = (wid >> 1)*16;
        float acc[2][2][4] = {};
#pragma unroll
        for (int kk = 0; kk < 16; ++kk){
            unsigned a[2][4];
#pragma unroll
            for (int mi = 0; mi < 2; ++mi){
                int base = (m0 + mi*16 + gid)*132 + kk*8 + tig;
                a[mi][0] = cvt_tf32(tang[base]);
                a[mi][1] = cvt_tf32(tang[base + 8*132]);
                a[mi][2] = cvt_tf32(tang[base + 4]);
                a[mi][3] = cvt_tf32(tang[base + 8*132 + 4]);
            }
            int kb = kk*8 + tig;
#pragma unroll
            for (int ni = 0; ni < 2; ++ni){
                int c = n0 + ni*8 + gid;
                unsigned b0 = cvt_tf32(__ldg(&W1[kb*64 + c]));
                unsigned b1 = cvt_tf32(__ldg(&W1[(kb+4)*64 + c]));
                mma_tf32(acc[0][ni], a[0], b0, b1);
                mma_tf32(acc[1][ni], a[1], b0, b1);
            }
        }
#pragma unroll
        for (int mi = 0; mi < 2; ++mi){
            float slo = 0.f, shi = 0.f;
#pragma unroll
            for (int ni = 0; ni < 2; ++ni){
                int c = n0 + ni*8 + tig*2;
                float w2a = __ldg(&W2[c]), w2b = __ldg(&W2[c+1]);
                float b1a = __ldg(&B1[c]), b1b = __ldg(&B1[c+1]);
                slo += fmaxf(acc[mi][ni][0] + b1a, 0.f)*w2a + fmaxf(acc[mi][ni][1] + b1b, 0.f)*w2b;
                shi += fmaxf(acc[mi][ni][2] + b1a, 0.f)*w2a + fmaxf(acc[mi][ni][3] + b1b, 0.f)*w2b;
            }
            slo += __shfl_xor_sync(0xffffffffu, slo, 1);
            slo += __shfl_xor_sync(0xffffffffu, slo, 2);
            shi += __shfl_xor_sync(0xffffffffu, shi, 1);
            shi += __shfl_xor_sync(0xffffffffu, shi, 2);
            if (tig == 0){
                atomicAdd(&av[m0 + mi*16 + gid],     slo);
                atomicAdd(&av[m0 + mi*16 + gid + 8], shi);
            }
        }
    }
    __syncthreads();

    if (wid == 0){
        const float b2 = B2[0];
        float a0 = ftanh(av[lane] + b2);
        float a1 = ftanh(av[lane+32] + b2);
        float mx = wmax(fmaxf(a0, a1));
        float e0 = __expf(a0 - mx), e1 = __expf(a1 - mx);
        float s = wsum(e0 + e1);
        wv[lane] = e0/s; wv[lane+32] = e1/s;
    }
    __syncthreads();

    if (tid < 64) av[tid] = wv[tid]*istg[tid];
    __syncthreads();
    {
        int j = tid & 63, q = tid >> 6;
        float a = 0.f;
#pragma unroll 4
        for (int mm = 0; mm < 16; ++mm){
            int m = q*16 + mm;
            a += av[m]*tang[m*132 + j];
        }
        pp[q*68 + j] = a;
    }
    __syncthreads();
    if (tid < 64) mp[tid] = pp[tid] + pp[68+tid] + pp[136+tid] + pp[204+tid];
    __syncthreads();
    if (wid == 0){
        float v = mp[lane]*mp[lane] + mp[lane+32]*mp[lane+32];
        v = wsum(v);
        if (lane == 0) scal[0] = v;
    }
    __syncthreads();
    {
        int m = tid & 63, q = tid >> 6;
        float a = 0.f;
#pragma unroll 4
        for (int jj = 0; jj < 16; ++jj){
            int j = q*16 + jj;
            a += hts[m*65 + j]*mp[j];
        }
        pp[q*68 + m] = a;
    }
    __syncthreads();
    if (tid < 64){
        float dsum = pp[tid] + pp[68+tid] + pp[136+tid] + pp[204+tid];
        float p2v = scal[0];
        float wm = wv[tid];
        float xy = -wm*dsum;
        float y2 = wm*wm*ht2s[tid];
        float c2v = 1.f - p2v;
        float c1v = 1.f + 2.f*xy + y2;
        float den = fmaxf(1.f + 2.f*xy + p2v*y2, 1e-15f);
        float invden = 1.f/den;
        float n2 = (c1v*c1v*p2v + 2.f*c1v*c2v*xy + c2v*c2v*y2)*invden*invden;
        float n = sqrtf(fmaxf(n2, 1e-15f));
        float lamp = 2.f/fmaxf(1.f - p2v, 1e-15f);
        float sc = (2.f/lamp)*fartanh_clip(n)/n;
        av[tid]   = wm*sc*c1v*invden;    // alv
        istg[tid] = wm*wm*sc*c2v*invden; // bev
    }
    __syncthreads();
    if (wid == 0){
        float sa = av[lane] + av[lane+32];
        sa = wsum(sa);
        if (lane == 0) scal[1] = sa;
    }
    __syncthreads();
    {
        int j = tid & 63, q = tid >> 6;
        float o = 0.f;
#pragma unroll 4
        for (int mm = 0; mm < 16; ++mm){
            int m = q*16 + mm;
            o += istg[m]*hts[m*65 + j];
        }
        pp[q*68 + j] = o;
    }
    __syncthreads();
    if (tid < 64)
        ht2s[tid] = (pp[tid] + pp[68+tid] + pp[136+tid] + pp[204+tid]) - mp[tid]*scal[1];
    __syncthreads();
    if (wid == 0){
        float v = ht2s[lane]*ht2s[lane] + ht2s[lane+32]*ht2s[lane+32];
        v = wsum(v);
        if (lane == 0) scal[2] = 1.f/fmaxf(sqrtf(v), 1e-12f);
    }
    __syncthreads();
    if (tid < 64){
        float o = ht2s[tid];
        g_embs[eidx(build, layer+1, b, tid)] = o;
        g_norm[eidx(build, layer+1, b, tid)] = o*scal[2];
    }
}

// ---------------- MLCL GEMM: 128x128 tiles, 3 CTAs/SM ----------------
#define ML_SMEM_FLOATS (128*68*2 + 256)
__global__ __launch_bounds__(256, 3) void mlcl_gemm(){
    const int pair = blockIdx.z;
    const float* A  = g_norm + (pair == 0 ? 0 : 1)*NPB;
    const float* Bn = g_norm + (pair == 0 ? 2 : 3)*NPB;
    float* rs = g_rowsum + pair*ROWS;
    float* cs = g_colsum + pair*ROWS;

    extern __shared__ float sm[];
    float* As = sm;                 // [128][68] tf32
    float* Bs = As + 128*68;        // [128][68] tf32
    float* rowpart = Bs + 128*68;   // [128]
    float* colpart = rowpart + 128; // [128]

    const int tid = threadIdx.x;
    const int by = blockIdx.y, bx = blockIdx.x;
    const int lane = tid & 31, wid = tid >> 5;
    const int gid = lane >> 2, tig = lane & 3;

    for (int e = tid; e < 2048; e += 256){
        int i = e >> 4, k4 = e & 15;
        float4 v = *(const float4*)&A[(by*128 + i)*64 + k4*4];
        *(float4*)&As[i*68 + k4*4] =
            make_float4(cvt_tf32f(v.x), cvt_tf32f(v.y), cvt_tf32f(v.z), cvt_tf32f(v.w));
        float4 w = *(const float4*)&Bn[(bx*128 + i)*64 + k4*4];
        *(float4*)&Bs[i*68 + k4*4] =
            make_float4(cvt_tf32f(w.x), cvt_tf32f(w.y), cvt_tf32f(w.z), cvt_tf32f(w.w));
    }
    if (tid < 128){ rowpart[tid] = 0.f; colpart[tid] = 0.f; }
    __syncthreads();

    const int m0 = (wid & 3)*32, n0 = (wid >> 2)*64;
    float acc[2][8][4] = {};
#pragma unroll
    for (int kk = 0; kk < 8; ++kk){
        unsigned a[2][4];
#pragma unroll
        for (int mi = 0; mi < 2; ++mi){
            int base = (m0 + mi*16 + gid)*68 + kk*8 + tig;
            a[mi][0] = __float_as_uint(As[base]);
            a[mi][1] = __float_as_uint(As[base + 8*68]);
            a[mi][2] = __float_as_uint(As[base + 4]);
            a[mi][3] = __float_as_uint(As[base + 8*68 + 4]);
        }
#pragma unroll
        for (int ni = 0; ni < 8; ++ni){
            int bb = (n0 + ni*8 + gid)*68 + kk*8 + tig;
            unsigned b0 = __float_as_uint(Bs[bb]);
            unsigned b1 = __float_as_uint(Bs[bb + 4]);
            mma_tf32(acc[0][ni], a[0], b0, b1);
            mma_tf32(acc[1][ni], a[1], b0, b1);
        }
    }

    float cl[8], ch[8];
#pragma unroll
    for (int ni = 0; ni < 8; ++ni){ cl[ni] = 0.f; ch[ni] = 0.f; }
#pragma unroll
    for (int mi = 0; mi < 2; ++mi){
        float rlo = 0.f, rhi = 0.f;
#pragma unroll
        for (int ni = 0; ni < 8; ++ni){
            float e0 = __expf(5.f*acc[mi][ni][0]);
            float e1 = __expf(5.f*acc[mi][ni][1]);
            float e2 = __expf(5.f*acc[mi][ni][2]);
            float e3 = __expf(5.f*acc[mi][ni][3]);
            rlo += e0 + e1; rhi += e2 + e3;
            cl[ni] += e0 + e2; ch[ni] += e1 + e3;
        }
        rlo += __shfl_xor_sync(0xffffffffu, rlo, 1);
        rlo += __shfl_xor_sync(0xffffffffu, rlo, 2);
        rhi += __shfl_xor_sync(0xffffffffu, rhi, 1);
        rhi += __shfl_xor_sync(0xffffffffu, rhi, 2);
        if (tig == 0){
            atomicAdd(&rowpart[m0 + mi*16 + gid],     rlo);
            atomicAdd(&rowpart[m0 + mi*16 + gid + 8], rhi);
        }
    }
#pragma unroll
    for (int ni = 0; ni < 8; ++ni){
        cl[ni] += __shfl_xor_sync(0xffffffffu, cl[ni], 4);
        cl[ni] += __shfl_xor_sync(0xffffffffu, cl[ni], 8);
        cl[ni] += __shfl_xor_sync(0xffffffffu, cl[ni], 16);
        ch[ni] += __shfl_xor_sync(0xffffffffu, ch[ni], 4);
        ch[ni] += __shfl_xor_sync(0xffffffffu, ch[ni], 8);
        ch[ni] += __shfl_xor_sync(0xffffffffu, ch[ni], 16);
        if (gid == 0){
            atomicAdd(&colpart[n0 + ni*8 + tig*2],     cl[ni]);
            atomicAdd(&colpart[n0 + ni*8 + tig*2 + 1], ch[ni]);
        }
    }
    __syncthreads();
    if (tid < 128){
        atomicAdd(&rs[by*128 + tid], rowpart[tid]);
        atomicAdd(&cs[bx*128 + tid], colpart[tid]);
    }
}

// ---------------- loss reduction ----------------
__global__ void loss_kernel(){
    const int wid = threadIdx.x >> 5, lane = threadIdx.x & 31;
    int r = blockIdx.x*8 + wid;
    int pair = r >= ROWS;
    int i = r - pair*ROWS;
    const float* A  = g_norm + (pair ? 1 : 0)*NPB;
    const float* Bn = g_norm + (pair ? 3 : 2)*NPB;
    float d = A[i*64 + lane]*Bn[i*64 + lane] + A[i*64 + lane + 32]*Bn[i*64 + lane + 32];
    d = wsum(d);
    __shared__ float red[8];
    if (lane == 0)
        red[wid] = logf(g_rowsum[pair*ROWS + i]) + logf(g_colsum[pair*ROWS + i]) - 10.f*d;
    __syncthreads();
    if (threadIdx.x == 0){
        float s = 0.f;
#pragma unroll
        for (int w = 0; w < 8; ++w) s += red[w];
        atomicAdd(&g_loss, s);
    }
}

// ---------------- scores + loss finalize ----------------
__global__ void scores_kernel(float* out, int out_size){
    int b = blockIdx.x*8 + (threadIdx.x >> 5);
    int lane = threadIdx.x & 31;
    if (blockIdx.x == 0 && threadIdx.x == 0 && out_size > Bq) out[Bq] = 1e-6f*g_loss;
    if (b >= Bq) return;
    float s = 0.f;
#pragma unroll
    for (int l = 0; l < 3; ++l){
        s += g_embs[eidx(0,l,b,lane)]   *g_embs[eidx(3,l,b,lane)]
           + g_embs[eidx(0,l,b,lane+32)]*g_embs[eidx(3,l,b,lane+32)]
           + g_embs[eidx(2,l,b,lane)]   *g_embs[eidx(1,l,b,lane)]
           + g_embs[eidx(2,l,b,lane+32)]*g_embs[eidx(1,l,b,lane+32)];
    }
    s = wsum(s);
    if (lane == 0) out[b] = 1.f/(1.f + expf(-s));
}

// ---------------- launch ----------------
extern "C" void kernel_launch(void* const* d_in, const int* in_sizes, int n_in,
                              void* d_out, int out_size){
    (void)in_sizes; (void)n_in;
    const int*   items  = (const int*)  d_in[0];
    const int*   ucf_h  = (const int*)  d_in[1];
    const int*   ucf_r  = (const int*)  d_in[2];
    const int*   ucf_t  = (const int*)  d_in[3];
    const int*   ikg_h  = (const int*)  d_in[4];
    const int*   ikg_r  = (const int*)  d_in[5];
    const int*   ikg_t  = (const int*)  d_in[6];
    const int*   ukg_h  = (const int*)  d_in[7];
    const int*   ukg_r  = (const int*)  d_in[8];
    const int*   ukg_t  = (const int*)  d_in[9];
    const int*   icf_h  = (const int*)  d_in[10];
    const int*   icf_r  = (const int*)  d_in[11];
    const int*   icf_t  = (const int*)  d_in[12];
    const float* E      = (const float*)d_in[13];
    const float* R      = (const float*)d_in[14];
    const float* att_w1 = (const float*)d_in[15];
    const float* att_w2 = (const float*)d_in[16];
    const float* a2_w1  = (const float*)d_in[17];
    const float* a2_b1  = (const float*)d_in[18];
    const float* a2_w2  = (const float*)d_in[19];
    const float* a2_b2  = (const float*)d_in[20];
    const float* curv   = (const float*)d_in[21];
    float* out = (float*)d_out;

    const int ed_smem = ED_SMEM_FLOATS*4;
    const int hy_smem = HY_SMEM_FLOATS*4;
    const int ml_smem = ML_SMEM_FLOATS*4;
    cudaFuncSetAttribute(ed_kernel,    cudaFuncAttributeMaxDynamicSharedMemorySize, ed_smem);
    cudaFuncSetAttribute(hyper_kernel, cudaFuncAttributeMaxDynamicSharedMemorySize, hy_smem);
    cudaFuncSetAttribute(mlcl_gemm,    cudaFuncAttributeMaxDynamicSharedMemorySize, ml_smem);

    zero_kernel<<<(2*ROWS + 1023)/1024, 1024>>>();
    init_kernel<<<Bq, 256>>>(E, items, ucf_h, ukg_h, icf_h);

    dim3 gb(Bq, 2, 2);
    ed_kernel<<<gb, 256, ed_smem>>>(E, R, ucf_h, ucf_r, ucf_t, ikg_h, ikg_r, ikg_t, att_w1, att_w2);
    hyper_kernel<<<gb, 256, hy_smem>>>(E, R, ukg_h, ukg_r, ukg_t, icf_h, icf_r, icf_t,
                                       a2_w1, a2_b1, a2_w2, a2_b2, curv);

    dim3 gg(48, 48, 2);
    mlcl_gemm<<<gg, 256, ml_smem>>>();
    loss_kernel<<<2*ROWS/8, 256>>>();
    scores_kernel<<<Bq/8, 256>>>(out, out_size);
}